// round 6
// baseline (speedup 1.0000x reference)
#include <cuda_runtime.h>
#include <cuda_bf16.h>
#include <cstdint>
#include <cstddef>

#define Bsz 16
#define Lsz 2048
#define Dsz 512
#define NLsz 4
#define Tsz (Bsz * Lsz)  // 32768
#define DD (Dsz * Dsz)

// weight arena offsets (units of DD)
#define W_CONV(i) ((size_t)(i) * 3 * DD)
#define W_WOUT(i) ((size_t)(12 + (i)) * DD)
#define W_FC(i)   ((size_t)(16 + 2 * (i)) * DD)
#define W_MO(i)   ((size_t)(24 + (i)) * DD)
#define W_HEAD    ((size_t)28 * DD)

// scan chunking
#define SCH 256
#define NCH (Lsz / SCH)  // 8

// ---------------- scratch (device globals; no allocation allowed) ----------
__device__ float g_y[Tsz * Dsz];
__device__ float g_z2[Tsz * Dsz];
__device__ float g_gate[Tsz];
__device__ float g_hend[NCH * Bsz * Dsz];
__device__ float g_aprod[NCH * Bsz * Dsz];
__device__ __nv_bfloat16 g_zh[Tsz * Dsz], g_zl[Tsz * Dsz];
__device__ __nv_bfloat16 g_hh[Tsz * Dsz], g_hl[Tsz * Dsz];
__device__ __nv_bfloat16 g_gh[Tsz * Dsz], g_gl[Tsz * Dsz];
__device__ __nv_bfloat16 g_wh[29 * DD], g_wl[29 * DD];

// ---------------- helpers ---------------------------------------------------
__device__ __forceinline__ uint32_t smem_u32(const void* p) {
    return (uint32_t)__cvta_generic_to_shared(p);
}
__device__ __forceinline__ uint32_t swz(uint32_t x) { return x ^ ((x >> 3) & 0x70); }

__device__ __forceinline__ void cp16(uint32_t dst, const void* src, bool v) {
    int sz = v ? 16 : 0;
    asm volatile("cp.async.cg.shared.global [%0], [%1], 16, %2;"
                 :: "r"(dst), "l"(src), "r"(sz) : "memory");
}
#define CP_COMMIT() asm volatile("cp.async.commit_group;" ::: "memory")

#define LDSM_X4(r, a)                                                          \
    asm volatile("ldmatrix.sync.aligned.m8n8.x4.shared.b16 {%0,%1,%2,%3}, [%4];" \
                 : "=r"((r)[0]), "=r"((r)[1]), "=r"((r)[2]), "=r"((r)[3]) : "r"(a))

#define MMA_BF16(d, a, b0, b1)                                                 \
    asm volatile(                                                              \
        "mma.sync.aligned.m16n8k16.row.col.f32.bf16.bf16.f32 "                 \
        "{%0,%1,%2,%3},{%4,%5,%6,%7},{%8,%9},{%0,%1,%2,%3};"                   \
        : "+f"((d)[0]), "+f"((d)[1]), "+f"((d)[2]), "+f"((d)[3])               \
        : "r"((a)[0]), "r"((a)[1]), "r"((a)[2]), "r"((a)[3]), "r"(b0), "r"(b1))

__device__ __forceinline__ void split2(float a, float b, __nv_bfloat162& hi,
                                       __nv_bfloat162& lo) {
    hi = __floats2bfloat162_rn(a, b);
    lo = __floats2bfloat162_rn(a - __bfloat162float(hi.x), b - __bfloat162float(hi.y));
}

// ============================================================================
// Generic bf16-split GEMM, 512 threads, tile 128x128, 16 warps (4Mx4N, 32x32).
// flags: 1=addBias, 2=accum fp32, 4=split bf16 out, 8=gate dot (atomicAdd),
//        16=one-hot residual add (layer-0 mo).
// ============================================================================
#define STAGE_B 65536
#define GSMEM (3 * STAGE_B)

__global__ __launch_bounds__(512, 1)
void mma_gemm_k(const __nv_bfloat16* __restrict__ Ah, const __nv_bfloat16* __restrict__ Al,
                const __nv_bfloat16* __restrict__ Wh, const __nv_bfloat16* __restrict__ Wl,
                const float* __restrict__ bias, float* __restrict__ Cf,
                __nv_bfloat16* __restrict__ Ch, __nv_bfloat16* __restrict__ Cl,
                const float* __restrict__ wgv, const int* __restrict__ xTok,
                float* __restrict__ gateOut,
                int N, int nPasses, int s0, int s1, int s2, int flags) {
    extern __shared__ char smem[];
    const uint32_t smb = smem_u32(smem);
    const int tid = threadIdx.x, lane = tid & 31, wid = tid >> 5;
    const int mBase = blockIdx.y << 7, nBase = blockIdx.x << 7;
    const int wm = wid & 3, wn = wid >> 2;

    float acc[2][4][4];
#pragma unroll
    for (int t = 0; t < 2; t++)
#pragma unroll
        for (int j = 0; j < 4; j++)
#pragma unroll
            for (int q = 0; q < 4; q++) acc[t][j][q] = 0.f;

    const int total = nPasses * 8;
    const int rowIdx = tid >> 3, col16 = tid & 7;

    auto issue = [&](int idx) {
        const int p = idx >> 3, c8 = idx & 7;
        const int shift = (p == 0) ? s0 : ((p == 1) ? s1 : s2);
        const size_t wOff = (size_t)p * DD;
        const uint32_t sb = smb + (uint32_t)(idx % 3) * STAGE_B;
        const int kOff = c8 * 64 + col16 * 8;
#pragma unroll
        for (int c = 0; c < 2; c++) {
            const int row = rowIdx + c * 64;
            const uint32_t dsw = swz((uint32_t)(row * 128 + col16 * 16));
            const int m = mBase + row;
            const int l = m & (Lsz - 1);
            const bool valid = ((unsigned)(l + shift) < (unsigned)Lsz);
            const size_t aoff = (size_t)(m + (valid ? shift : 0)) * Dsz + kOff;
            cp16(sb + dsw, Ah + aoff, valid);
            cp16(sb + 16384 + dsw, Al + aoff, valid);
            const size_t woff = wOff + (size_t)(nBase + row) * Dsz + kOff;
            cp16(sb + 32768 + dsw, Wh + woff, true);
            cp16(sb + 49152 + dsw, Wl + woff, true);
        }
        CP_COMMIT();
    };

    issue(0);
    if (total > 1) issue(1);
    for (int idx = 0; idx < total; idx++) {
        if (idx + 2 < total) {
            issue(idx + 2);
            asm volatile("cp.async.wait_group 2;" ::: "memory");
        } else if (idx + 1 < total) {
            asm volatile("cp.async.wait_group 1;" ::: "memory");
        } else {
            asm volatile("cp.async.wait_group 0;" ::: "memory");
        }
        __syncthreads();
        const uint32_t sb = smb + (uint32_t)(idx % 3) * STAGE_B;
#pragma unroll
        for (int kk = 0; kk < 4; kk++) {
            uint32_t ah[2][4], al[2][4];
#pragma unroll
            for (int t = 0; t < 2; t++) {
                const int row = wm * 32 + t * 16 + (lane & 15);
                const uint32_t off =
                    swz((uint32_t)(row * 128 + kk * 32 + (lane >> 4) * 16));
                LDSM_X4(ah[t], sb + off);
                LDSM_X4(al[t], sb + 16384 + off);
            }
#pragma unroll
            for (int jp = 0; jp < 2; jp++) {
                const int nrow = wn * 32 + jp * 16 + (lane & 7) + ((lane >> 4) << 3);
                const uint32_t off =
                    swz((uint32_t)(nrow * 128 + kk * 32 + ((lane >> 3) & 1) * 16));
                uint32_t bh[4], bl[4];
                LDSM_X4(bh, sb + 32768 + off);
                LDSM_X4(bl, sb + 49152 + off);
#pragma unroll
                for (int t = 0; t < 2; t++) {
#pragma unroll
                    for (int jj = 0; jj < 2; jj++) {
                        float* d = acc[t][jp * 2 + jj];
                        MMA_BF16(d, ah[t], bh[jj * 2], bh[jj * 2 + 1]);
                        MMA_BF16(d, ah[t], bl[jj * 2], bl[jj * 2 + 1]);
                        MMA_BF16(d, al[t], bh[jj * 2], bh[jj * 2 + 1]);
                    }
                }
            }
        }
        __syncthreads();
    }

    const bool addB = (flags & 1) != 0;
    const bool accum = (flags & 2) != 0;
    const bool splitO = (flags & 4) != 0;
    const bool gateDot = (flags & 8) != 0;
    const bool onehot = (flags & 16) != 0;
#pragma unroll
    for (int t = 0; t < 2; t++) {
        const int r0 = mBase + wm * 32 + t * 16 + (lane >> 2);
        float p0 = 0.f, p1 = 0.f;
#pragma unroll
        for (int j = 0; j < 4; j++) {
            const int col = nBase + wn * 32 + j * 8 + (lane & 3) * 2;
            float b0 = 0.f, b1 = 0.f;
            if (addB) { b0 = bias[col]; b1 = bias[col + 1]; }
            float v0 = acc[t][j][0] + b0, v1 = acc[t][j][1] + b1;
            float v2 = acc[t][j][2] + b0, v3 = acc[t][j][3] + b1;
            const size_t o0 = (size_t)r0 * N + col;
            const size_t o1 = (size_t)(r0 + 8) * N + col;
            if (splitO) {
                __nv_bfloat162 h, lo;
                split2(v0, v1, h, lo);
                *(__nv_bfloat162*)(Ch + o0) = h;
                *(__nv_bfloat162*)(Cl + o0) = lo;
                split2(v2, v3, h, lo);
                *(__nv_bfloat162*)(Ch + o1) = h;
                *(__nv_bfloat162*)(Cl + o1) = lo;
            } else {
                if (onehot) {
                    const int t0 = xTok[r0], t1 = xTok[r0 + 8];
                    v0 += (col == t0) ? 1.f : 0.f;
                    v1 += (col + 1 == t0) ? 1.f : 0.f;
                    v2 += (col == t1) ? 1.f : 0.f;
                    v3 += (col + 1 == t1) ? 1.f : 0.f;
                }
                if (accum) {
                    float2 q0 = *(float2*)(Cf + o0);
                    float2 q1 = *(float2*)(Cf + o1);
                    v0 += q0.x; v1 += q0.y; v2 += q1.x; v3 += q1.y;
                }
                *(float2*)(Cf + o0) = make_float2(v0, v1);
                *(float2*)(Cf + o1) = make_float2(v2, v3);
            }
            if (gateDot) {
                const float w0 = __ldg(wgv + col), w1 = __ldg(wgv + col + 1);
                p0 = fmaf(v0, w0, fmaf(v1, w1, p0));
                p1 = fmaf(v2, w0, fmaf(v3, w1, p1));
            }
        }
        if (gateDot) {
            p0 += __shfl_xor_sync(0xffffffffu, p0, 1);
            p0 += __shfl_xor_sync(0xffffffffu, p0, 2);
            p1 += __shfl_xor_sync(0xffffffffu, p1, 1);
            p1 += __shfl_xor_sync(0xffffffffu, p1, 2);
            if ((lane & 3) == 0) {
                atomicAdd(gateOut + r0, p0);
                atomicAdd(gateOut + r0 + 8, p1);
            }
        }
    }
}

// ============================================================================
// Fused fc + gated-MLP GEMM, 512 threads.
// ============================================================================
#define FC_STAGE 98304
#define FCSMEM (2 * FC_STAGE)

__global__ __launch_bounds__(512, 1)
void mma_fc_k(const __nv_bfloat16* __restrict__ Ah, const __nv_bfloat16* __restrict__ Al,
              const __nv_bfloat16* __restrict__ Wh, const __nv_bfloat16* __restrict__ Wl,
              const float* __restrict__ bias,
              __nv_bfloat16* __restrict__ Oh, __nv_bfloat16* __restrict__ Ol) {
    extern __shared__ char smem[];
    const uint32_t smb = smem_u32(smem);
    const int tid = threadIdx.x, lane = tid & 31, wid = tid >> 5;
    const int mBase = blockIdx.y << 7, nBase = blockIdx.x << 7;
    const int wm = wid & 3, wn = wid >> 2;

    float accg[2][4][4], accv[2][4][4];
#pragma unroll
    for (int t = 0; t < 2; t++)
#pragma unroll
        for (int j = 0; j < 4; j++)
#pragma unroll
            for (int q = 0; q < 4; q++) { accg[t][j][q] = 0.f; accv[t][j][q] = 0.f; }

    const int rowIdx = tid >> 3, col16 = tid & 7;

    auto issue = [&](int idx) {
        const int c8 = idx & 7;
        const uint32_t sb = smb + (uint32_t)(idx & 1) * FC_STAGE;
        const int kOff = c8 * 64 + col16 * 8;
#pragma unroll
        for (int c = 0; c < 2; c++) {
            const int row = rowIdx + c * 64;
            const uint32_t dsw = swz((uint32_t)(row * 128 + col16 * 16));
            const size_t aoff = (size_t)(mBase + row) * Dsz + kOff;
            cp16(sb + dsw, Ah + aoff, true);
            cp16(sb + 16384 + dsw, Al + aoff, true);
            const size_t wgoff = (size_t)(nBase + row) * Dsz + kOff;
            cp16(sb + 32768 + dsw, Wh + wgoff, true);
            cp16(sb + 49152 + dsw, Wl + wgoff, true);
            const size_t wvoff = (size_t)(512 + nBase + row) * Dsz + kOff;
            cp16(sb + 65536 + dsw, Wh + wvoff, true);
            cp16(sb + 81920 + dsw, Wl + wvoff, true);
        }
        CP_COMMIT();
    };

    issue(0);
    for (int idx = 0; idx < 8; idx++) {
        if (idx + 1 < 8) {
            issue(idx + 1);
            asm volatile("cp.async.wait_group 1;" ::: "memory");
        } else {
            asm volatile("cp.async.wait_group 0;" ::: "memory");
        }
        __syncthreads();
        const uint32_t sb = smb + (uint32_t)(idx & 1) * FC_STAGE;
#pragma unroll
        for (int kk = 0; kk < 4; kk++) {
            uint32_t ah[2][4], al[2][4];
#pragma unroll
            for (int t = 0; t < 2; t++) {
                const int row = wm * 32 + t * 16 + (lane & 15);
                const uint32_t off =
                    swz((uint32_t)(row * 128 + kk * 32 + (lane >> 4) * 16));
                LDSM_X4(ah[t], sb + off);
                LDSM_X4(al[t], sb + 16384 + off);
            }
#pragma unroll
            for (int jp = 0; jp < 2; jp++) {
                const int nrow = wn * 32 + jp * 16 + (lane & 7) + ((lane >> 4) << 3);
                const uint32_t off =
                    swz((uint32_t)(nrow * 128 + kk * 32 + ((lane >> 3) & 1) * 16));
                {
                    uint32_t bh[4], bl[4];
                    LDSM_X4(bh, sb + 32768 + off);
                    LDSM_X4(bl, sb + 49152 + off);
#pragma unroll
                    for (int t = 0; t < 2; t++)
#pragma unroll
                        for (int jj = 0; jj < 2; jj++) {
                            float* d = accg[t][jp * 2 + jj];
                            MMA_BF16(d, ah[t], bh[jj * 2], bh[jj * 2 + 1]);
                            MMA_BF16(d, ah[t], bl[jj * 2], bl[jj * 2 + 1]);
                            MMA_BF16(d, al[t], bh[jj * 2], bh[jj * 2 + 1]);
                        }
                }
                {
                    uint32_t bh[4], bl[4];
                    LDSM_X4(bh, sb + 65536 + off);
                    LDSM_X4(bl, sb + 81920 + off);
#pragma unroll
                    for (int t = 0; t < 2; t++)
#pragma unroll
                        for (int jj = 0; jj < 2; jj++) {
                            float* d = accv[t][jp * 2 + jj];
                            MMA_BF16(d, ah[t], bh[jj * 2], bh[jj * 2 + 1]);
                            MMA_BF16(d, ah[t], bl[jj * 2], bl[jj * 2 + 1]);
                            MMA_BF16(d, al[t], bh[jj * 2], bh[jj * 2 + 1]);
                        }
                }
            }
        }
        __syncthreads();
    }

#pragma unroll
    for (int t = 0; t < 2; t++) {
#pragma unroll
        for (int j = 0; j < 4; j++) {
            const int r0 = mBase + wm * 32 + t * 16 + (lane >> 2);
            const int col = nBase + wn * 32 + j * 8 + (lane & 3) * 2;
            const float bg0 = bias[col], bg1 = bias[col + 1];
            const float bv0 = bias[512 + col], bv1 = bias[512 + col + 1];
            float s0 = 1.f / (1.f + expf(-(accg[t][j][0] + bg0)));
            float s1 = 1.f / (1.f + expf(-(accg[t][j][1] + bg1)));
            float s2 = 1.f / (1.f + expf(-(accg[t][j][2] + bg0)));
            float s3 = 1.f / (1.f + expf(-(accg[t][j][3] + bg1)));
            float v0 = s0 * (accv[t][j][0] + bv0);
            float v1 = s1 * (accv[t][j][1] + bv1);
            float v2 = s2 * (accv[t][j][2] + bv0);
            float v3 = s3 * (accv[t][j][3] + bv1);
            const size_t o0 = (size_t)r0 * Dsz + col;
            const size_t o1 = (size_t)(r0 + 8) * Dsz + col;
            __nv_bfloat162 h, lo;
            split2(v0, v1, h, lo);
            *(__nv_bfloat162*)(Oh + o0) = h;
            *(__nv_bfloat162*)(Ol + o0) = lo;
            split2(v2, v3, h, lo);
            *(__nv_bfloat162*)(Oh + o1) = h;
            *(__nv_bfloat162*)(Ol + o1) = lo;
        }
    }
}

// ---------------- layer-0 LN: analytic LN of one-hot ------------------------
__global__ void ln0_split_k(const int* __restrict__ x,
                            __nv_bfloat16* __restrict__ oh, __nv_bfloat16* __restrict__ ol,
                            const float* __restrict__ gamma, const float* __restrict__ beta) {
    int t = blockIdx.x, tid = threadIdx.x;
    const int tok = x[t];
    const float mean = 1.0f / 512.0f;
    const float var = (1.0f / 512.0f) * (511.0f / 512.0f);
    const float rstd = rsqrtf(var + 1e-5f);
    float4 g4 = ((const float4*)gamma)[tid];
    float4 b4 = ((const float4*)beta)[tid];
    int d0 = tid * 4;
    float f0 = (((d0 + 0) == tok ? 1.f : 0.f) - mean) * rstd * g4.x + b4.x;
    float f1 = (((d0 + 1) == tok ? 1.f : 0.f) - mean) * rstd * g4.y + b4.y;
    float f2 = (((d0 + 2) == tok ? 1.f : 0.f) - mean) * rstd * g4.z + b4.z;
    float f3 = (((d0 + 3) == tok ? 1.f : 0.f) - mean) * rstd * g4.w + b4.w;
    __nv_bfloat162 h01, l01, h23, l23;
    split2(f0, f1, h01, l01);
    split2(f2, f3, h23, l23);
    __nv_bfloat162* ph = (__nv_bfloat162*)(oh + (size_t)t * Dsz);
    __nv_bfloat162* pl = (__nv_bfloat162*)(ol + (size_t)t * Dsz);
    ph[2 * tid] = h01; ph[2 * tid + 1] = h23;
    pl[2 * tid] = l01; pl[2 * tid + 1] = l23;
}

// ---------------- layernorm with fused bf16 hi/lo split ----------------------
__global__ void ln_split_k(const float* __restrict__ in,
                           __nv_bfloat16* __restrict__ oh, __nv_bfloat16* __restrict__ ol,
                           const float* __restrict__ gamma, const float* __restrict__ beta) {
    int t = blockIdx.x, tid = threadIdx.x;
    const float4* rp = (const float4*)(in + (size_t)t * Dsz);
    float4 v = rp[tid];
    float s = v.x + v.y + v.z + v.w;
#pragma unroll
    for (int o = 16; o; o >>= 1) s += __shfl_xor_sync(0xffffffffu, s, o);
    __shared__ float smr[4];
    if ((tid & 31) == 0) smr[tid >> 5] = s;
    __syncthreads();
    float mean = (smr[0] + smr[1] + smr[2] + smr[3]) * (1.0f / Dsz);
    float dx = v.x - mean, dy = v.y - mean, dz = v.z - mean, dw = v.w - mean;
    float q = dx * dx + dy * dy + dz * dz + dw * dw;
#pragma unroll
    for (int o = 16; o; o >>= 1) q += __shfl_xor_sync(0xffffffffu, q, o);
    __syncthreads();
    if ((tid & 31) == 0) smr[tid >> 5] = q;
    __syncthreads();
    float var = (smr[0] + smr[1] + smr[2] + smr[3]) * (1.0f / Dsz);
    float rstd = rsqrtf(var + 1e-5f);
    float4 g4 = ((const float4*)gamma)[tid];
    float4 b4 = ((const float4*)beta)[tid];
    float f0 = dx * rstd * g4.x + b4.x, f1 = dy * rstd * g4.y + b4.y;
    float f2 = dz * rstd * g4.z + b4.z, f3 = dw * rstd * g4.w + b4.w;
    __nv_bfloat162 h01, l01, h23, l23;
    split2(f0, f1, h01, l01);
    split2(f2, f3, h23, l23);
    __nv_bfloat162* ph = (__nv_bfloat162*)(oh + (size_t)t * Dsz);
    __nv_bfloat162* pl = (__nv_bfloat162*)(ol + (size_t)t * Dsz);
    ph[2 * tid] = h01; ph[2 * tid + 1] = h23;
    pl[2 * tid] = l01; pl[2 * tid + 1] = l23;
}

// ---------------- conv weight repack + split ---------------------------------
__global__ void cwsplit_k(const float* __restrict__ cw,
                          __nv_bfloat16* __restrict__ wh, __nv_bfloat16* __restrict__ wl) {
    int idx = blockIdx.x * blockDim.x + threadIdx.x;
    int layer = idx / (3 * DD);
    int r = idx - layer * (3 * DD);
    int h = r / DD;
    int rr = r - h * DD;
    int o = rr >> 9, i = rr & 511;
    float v = cw[(size_t)layer * 3 * DD + ((size_t)o * Dsz + i) * 3 + h];
    __nv_bfloat16 hi = __float2bfloat16(v);
    wh[idx] = hi;
    wl[idx] = __float2bfloat16(v - __bfloat162float(hi));
}

// ---------------- generic weight split ---------------------------------------
__global__ void wsplit_k(const float* __restrict__ w, __nv_bfloat16* __restrict__ wh,
                         __nv_bfloat16* __restrict__ wl, int n) {
    int idx = blockIdx.x * blockDim.x + threadIdx.x;
    if (idx >= n) return;
    float v = w[idx];
    __nv_bfloat16 hi = __float2bfloat16(v);
    wh[idx] = hi;
    wl[idx] = __float2bfloat16(v - __bfloat162float(hi));
}

// ---------------- gate zero + sigmoid finish ----------------------------------
__global__ void zero_gate_k(float* __restrict__ g) {
    g[blockIdx.x * blockDim.x + threadIdx.x] = 0.f;
}
__global__ void sigmoid_gate_k(float* __restrict__ g, const float* __restrict__ bg) {
    int t = blockIdx.x * blockDim.x + threadIdx.x;
    g[t] = 1.0f / (1.0f + expf(-(g[t] + bg[0])));
}

// ---------------- chunked scan: phase 1 ---------------------------------------
__global__ void scan1_k(const float* __restrict__ x, const float* __restrict__ g,
                        float* __restrict__ hend, float* __restrict__ aprod) {
    int bx = blockIdx.x;
    int c = bx >> 6;
    int rem = bx & 63;
    int b = rem >> 2;
    int d = ((rem & 3) << 7) + threadIdx.x;
    size_t base = (size_t)b * Lsz * Dsz + d;
    const float* gb = g + (size_t)b * Lsz;
    const int l0 = c * SCH;
    float hv = 0.f, ap = 1.f;
    for (int l = l0; l < l0 + SCH; l += 8) {
        float xs[8], gs[8];
#pragma unroll
        for (int j = 0; j < 8; j++) {
            xs[j] = x[base + (size_t)(l + j) * Dsz];
            gs[j] = gb[l + j];
        }
#pragma unroll
        for (int j = 0; j < 8; j++) {
            hv = fmaf(gs[j], xs[j] - hv, hv);
            ap *= (1.f - gs[j]);
        }
    }
    const size_t o = (size_t)c * (Bsz * Dsz) + (size_t)b * Dsz + d;
    hend[o] = hv;
    aprod[o] = ap;
}

// ---------------- chunked scan: phase 2+3 fused (carry inline) -----------------
__global__ void scan3_k(const float* __restrict__ x, const float* __restrict__ g,
                        const float* __restrict__ hend, const float* __restrict__ aprod,
                        __nv_bfloat16* __restrict__ hh, __nv_bfloat16* __restrict__ hl) {
    int bx = blockIdx.x;
    int c = bx >> 6;
    int rem = bx & 63;
    int b = rem >> 2;
    int d = ((rem & 3) << 7) + threadIdx.x;
    size_t base = (size_t)b * Lsz * Dsz + d;
    const float* gb = g + (size_t)b * Lsz;
    // inline carry: replay chunk summaries 0..c-1
    float hv = 0.f;
    for (int cc = 0; cc < c; cc++) {
        const size_t o = (size_t)cc * (Bsz * Dsz) + (size_t)b * Dsz + d;
        hv = hend[o] + aprod[o] * hv;
    }
    const int l0 = c * SCH;
    for (int l = l0; l < l0 + SCH; l += 8) {
        float xs[8], gs[8];
#pragma unroll
        for (int j = 0; j < 8; j++) {
            xs[j] = x[base + (size_t)(l + j) * Dsz];
            gs[j] = gb[l + j];
        }
#pragma unroll
        for (int j = 0; j < 8; j++) {
            hv = fmaf(gs[j], xs[j] - hv, hv);
            __nv_bfloat16 hi = __float2bfloat16(hv);
            size_t o = base + (size_t)(l + j) * Dsz;
            hh[o] = hi;
            hl[o] = __float2bfloat16(hv - __bfloat162float(hi));
        }
    }
}

// ---------------- launch --------------------------------------------------------
extern "C" void kernel_launch(void* const* d_in, const int* in_sizes, int n_in,
                              void* d_out, int out_size) {
    const int* x = (const int*)d_in[0];
    const float* ln_g = (const float*)d_in[1];
    const float* ln_b = (const float*)d_in[2];
    const float* conv_w = (const float*)d_in[3];
    const float* conv_b = (const float*)d_in[4];
    const float* wg = (const float*)d_in[5];
    const float* bg = (const float*)d_in[6];
    const float* wout = (const float*)d_in[7];
    const float* bout = (const float*)d_in[8];
    const float* fc_w = (const float*)d_in[9];
    const float* fc_b = (const float*)d_in[10];
    const float* mo_w = (const float*)d_in[11];
    const float* mo_b = (const float*)d_in[12];
    const float* lnf_g = (const float*)d_in[13];
    const float* lnf_b = (const float*)d_in[14];
    const float* head_w = (const float*)d_in[15];
    const float* head_b = (const float*)d_in[16];

    float *y, *z2, *gt, *hend, *aprod;
    __nv_bfloat16 *zh, *zl, *hh, *hl, *gh, *gl, *wh, *wl;
    cudaGetSymbolAddress((void**)&y, g_y);
    cudaGetSymbolAddress((void**)&z2, g_z2);
    cudaGetSymbolAddress((void**)&gt, g_gate);
    cudaGetSymbolAddress((void**)&hend, g_hend);
    cudaGetSymbolAddress((void**)&aprod, g_aprod);
    cudaGetSymbolAddress((void**)&zh, g_zh);
    cudaGetSymbolAddress((void**)&zl, g_zl);
    cudaGetSymbolAddress((void**)&hh, g_hh);
    cudaGetSymbolAddress((void**)&hl, g_hl);
    cudaGetSymbolAddress((void**)&gh, g_gh);
    cudaGetSymbolAddress((void**)&gl, g_gl);
    cudaGetSymbolAddress((void**)&wh, g_wh);
    cudaGetSymbolAddress((void**)&wl, g_wl);

    cudaFuncSetAttribute(mma_gemm_k, cudaFuncAttributeMaxDynamicSharedMemorySize, GSMEM);
    cudaFuncSetAttribute(mma_fc_k, cudaFuncAttributeMaxDynamicSharedMemorySize, FCSMEM);

    const dim3 g512(4, Tsz / 128);

    // ---- one-time: weight splits ----
    cwsplit_k<<<(NLsz * 3 * DD) / 256, 256>>>(conv_w, wh + W_CONV(0), wl + W_CONV(0));
    wsplit_k<<<(NLsz * DD) / 256, 256>>>(wout, wh + W_WOUT(0), wl + W_WOUT(0), NLsz * DD);
    wsplit_k<<<(NLsz * 2 * DD) / 256, 256>>>(fc_w, wh + W_FC(0), wl + W_FC(0), NLsz * 2 * DD);
    wsplit_k<<<(NLsz * DD) / 256, 256>>>(mo_w, wh + W_MO(0), wl + W_MO(0), NLsz * DD);
    wsplit_k<<<DD / 256, 256>>>(head_w, wh + W_HEAD, wl + W_HEAD, DD);

    for (int i = 0; i < NLsz; i++) {
        if (i == 0)
            ln0_split_k<<<Tsz, 128>>>(x, zh, zl, ln_g, ln_b);
        else
            ln_split_k<<<Tsz, 128>>>(y, zh, zl, ln_g + (size_t)i * Dsz, ln_b + (size_t)i * Dsz);
        zero_gate_k<<<Tsz / 256, 256>>>(gt);
        // conv: 3 shifted passes, epilogue also reduces the gate dot
        mma_gemm_k<<<g512, 512, GSMEM>>>(zh, zl, wh + W_CONV(i), wl + W_CONV(i),
                                         conv_b + (size_t)i * Dsz, z2, nullptr, nullptr,
                                         wg + (size_t)i * Dsz, nullptr, gt,
                                         Dsz, 3, -1, 0, 1, 1 | 8);
        sigmoid_gate_k<<<Tsz / 256, 256>>>(gt, bg + i);
        scan1_k<<<NCH * 64, 128>>>(z2, gt, hend, aprod);
        scan3_k<<<NCH * 64, 128>>>(z2, gt, hend, aprod, hh, hl);
        // wout: split-bf16 output into zh/zl
        mma_gemm_k<<<g512, 512, GSMEM>>>(hh, hl, wh + W_WOUT(i), wl + W_WOUT(i),
                                         bout + (size_t)i * Dsz, nullptr, zh, zl,
                                         nullptr, nullptr, nullptr,
                                         Dsz, 1, 0, 0, 0, 5);
        // fc + gated-MLP fused
        mma_fc_k<<<g512, 512, FCSMEM>>>(zh, zl, wh + W_FC(i), wl + W_FC(i),
                                        fc_b + (size_t)i * 2 * Dsz, gh, gl);
        // mo: layer 0 adds analytic one-hot residual; others accumulate y
        mma_gemm_k<<<g512, 512, GSMEM>>>(gh, gl, wh + W_MO(i), wl + W_MO(i),
                                         mo_b + (size_t)i * Dsz, y, nullptr, nullptr,
                                         nullptr, (i == 0) ? x : nullptr, nullptr,
                                         Dsz, 1, 0, 0, 0, (i == 0) ? (1 | 16) : (1 | 2));
    }

    ln_split_k<<<Tsz, 128>>>(y, zh, zl, lnf_g, lnf_b);
    mma_gemm_k<<<g512, 512, GSMEM>>>(zh, zl, wh + W_HEAD, wl + W_HEAD, head_b,
                                     (float*)d_out, nullptr, nullptr,
                                     nullptr, nullptr, nullptr, Dsz, 1, 0, 0, 0, 1);
}

// round 7
// speedup vs baseline: 1.1591x; 1.1591x over previous
#include <cuda_runtime.h>
#include <cuda_bf16.h>
#include <cstdint>
#include <cstddef>

#define Bsz 16
#define Lsz 2048
#define Dsz 512
#define NLsz 4
#define Tsz (Bsz * Lsz)  // 32768
#define DD (Dsz * Dsz)

// weight arena offsets (units of DD)
#define W_CONV(i) ((size_t)(i) * 3 * DD)
#define W_WOUT(i) ((size_t)(12 + (i)) * DD)   // holds wout^T (prep only)
#define W_FC(i)   ((size_t)(16 + 2 * (i)) * DD)  // after prep: Wcomb = Wf@Wo
#define W_MO(i)   ((size_t)(24 + (i)) * DD)
#define W_HEAD    ((size_t)28 * DD)

// scan chunking
#define SCH 256
#define NCH (Lsz / SCH)  // 8

// ---------------- scratch (device globals; no allocation allowed) ----------
__device__ float g_y[Tsz * Dsz];
__device__ float g_z2[Tsz * Dsz];
__device__ float g_gate[Tsz];
__device__ float g_gatep[16 * Tsz];          // per-(nTile,warp) gate partials
__device__ float g_bcomb[NLsz * 2 * Dsz];    // Wf·bo + fb
__device__ float g_hend[NCH * Bsz * Dsz];
__device__ float g_aprod[NCH * Bsz * Dsz];
__device__ __nv_bfloat16 g_zh[Tsz * Dsz], g_zl[Tsz * Dsz];
__device__ __nv_bfloat16 g_hh[Tsz * Dsz], g_hl[Tsz * Dsz];
__device__ __nv_bfloat16 g_gh[Tsz * Dsz], g_gl[Tsz * Dsz];
__device__ __nv_bfloat16 g_wh[29 * DD], g_wl[29 * DD];

// ---------------- helpers ---------------------------------------------------
__device__ __forceinline__ uint32_t smem_u32(const void* p) {
    return (uint32_t)__cvta_generic_to_shared(p);
}
__device__ __forceinline__ uint32_t swz(uint32_t x) { return x ^ ((x >> 3) & 0x70); }

__device__ __forceinline__ void cp16(uint32_t dst, const void* src, bool v) {
    int sz = v ? 16 : 0;
    asm volatile("cp.async.cg.shared.global [%0], [%1], 16, %2;"
                 :: "r"(dst), "l"(src), "r"(sz) : "memory");
}
#define CP_COMMIT() asm volatile("cp.async.commit_group;" ::: "memory")

#define LDSM_X4(r, a)                                                          \
    asm volatile("ldmatrix.sync.aligned.m8n8.x4.shared.b16 {%0,%1,%2,%3}, [%4];" \
                 : "=r"((r)[0]), "=r"((r)[1]), "=r"((r)[2]), "=r"((r)[3]) : "r"(a))

#define MMA_BF16(d, a, b0, b1)                                                 \
    asm volatile(                                                              \
        "mma.sync.aligned.m16n8k16.row.col.f32.bf16.bf16.f32 "                 \
        "{%0,%1,%2,%3},{%4,%5,%6,%7},{%8,%9},{%0,%1,%2,%3};"                   \
        : "+f"((d)[0]), "+f"((d)[1]), "+f"((d)[2]), "+f"((d)[3])               \
        : "r"((a)[0]), "r"((a)[1]), "r"((a)[2]), "r"((a)[3]), "r"(b0), "r"(b1))

__device__ __forceinline__ void split2(float a, float b, __nv_bfloat162& hi,
                                       __nv_bfloat162& lo) {
    hi = __floats2bfloat162_rn(a, b);
    lo = __floats2bfloat162_rn(a - __bfloat162float(hi.x), b - __bfloat162float(hi.y));
}

// ============================================================================
// Generic bf16-split GEMM, 512 threads, tile 128x128.
// flags: 1=addBias, 2=accum fp32, 4=split bf16 out, 8=gate partials,
//        16=one-hot residual add (layer-0 mo).
// wLayerStride: extra W offset per 1024 M-rows (batched weight-prep GEMM).
// ============================================================================
#define STAGE_B 65536
#define GSMEM (3 * STAGE_B)

__global__ __launch_bounds__(512, 1)
void mma_gemm_k(const __nv_bfloat16* __restrict__ Ah, const __nv_bfloat16* __restrict__ Al,
                const __nv_bfloat16* __restrict__ Wh, const __nv_bfloat16* __restrict__ Wl,
                const float* __restrict__ bias, float* __restrict__ Cf,
                __nv_bfloat16* __restrict__ Ch, __nv_bfloat16* __restrict__ Cl,
                const float* __restrict__ wgv, const int* __restrict__ xTok,
                float* __restrict__ gateOut,
                int N, int nPasses, int s0, int s1, int s2, int flags,
                int wLayerStride) {
    extern __shared__ char smem[];
    const uint32_t smb = smem_u32(smem);
    const int tid = threadIdx.x, lane = tid & 31, wid = tid >> 5;
    const int mBase = blockIdx.y << 7, nBase = blockIdx.x << 7;
    const int wm = wid & 3, wn = wid >> 2;

    float acc[2][4][4];
#pragma unroll
    for (int t = 0; t < 2; t++)
#pragma unroll
        for (int j = 0; j < 4; j++)
#pragma unroll
            for (int q = 0; q < 4; q++) acc[t][j][q] = 0.f;

    const int total = nPasses * 8;
    const int rowIdx = tid >> 3, col16 = tid & 7;

    auto issue = [&](int idx) {
        const int p = idx >> 3, c8 = idx & 7;
        const int shift = (p == 0) ? s0 : ((p == 1) ? s1 : s2);
        const size_t wOff = (size_t)p * DD + (size_t)(mBase >> 10) * wLayerStride;
        const uint32_t sb = smb + (uint32_t)(idx % 3) * STAGE_B;
        const int kOff = c8 * 64 + col16 * 8;
#pragma unroll
        for (int c = 0; c < 2; c++) {
            const int row = rowIdx + c * 64;
            const uint32_t dsw = swz((uint32_t)(row * 128 + col16 * 16));
            const int m = mBase + row;
            const int l = m & (Lsz - 1);
            const bool valid = ((unsigned)(l + shift) < (unsigned)Lsz);
            const size_t aoff = (size_t)(m + (valid ? shift : 0)) * Dsz + kOff;
            cp16(sb + dsw, Ah + aoff, valid);
            cp16(sb + 16384 + dsw, Al + aoff, valid);
            const size_t woff = wOff + (size_t)(nBase + row) * Dsz + kOff;
            cp16(sb + 32768 + dsw, Wh + woff, true);
            cp16(sb + 49152 + dsw, Wl + woff, true);
        }
        CP_COMMIT();
    };

    issue(0);
    if (total > 1) issue(1);
    for (int idx = 0; idx < total; idx++) {
        if (idx + 2 < total) {
            issue(idx + 2);
            asm volatile("cp.async.wait_group 2;" ::: "memory");
        } else if (idx + 1 < total) {
            asm volatile("cp.async.wait_group 1;" ::: "memory");
        } else {
            asm volatile("cp.async.wait_group 0;" ::: "memory");
        }
        __syncthreads();
        const uint32_t sb = smb + (uint32_t)(idx % 3) * STAGE_B;
#pragma unroll
        for (int kk = 0; kk < 4; kk++) {
            uint32_t ah[2][4], al[2][4];
#pragma unroll
            for (int t = 0; t < 2; t++) {
                const int row = wm * 32 + t * 16 + (lane & 15);
                const uint32_t off =
                    swz((uint32_t)(row * 128 + kk * 32 + (lane >> 4) * 16));
                LDSM_X4(ah[t], sb + off);
                LDSM_X4(al[t], sb + 16384 + off);
            }
#pragma unroll
            for (int jp = 0; jp < 2; jp++) {
                const int nrow = wn * 32 + jp * 16 + (lane & 7) + ((lane >> 4) << 3);
                const uint32_t off =
                    swz((uint32_t)(nrow * 128 + kk * 32 + ((lane >> 3) & 1) * 16));
                uint32_t bh[4], bl[4];
                LDSM_X4(bh, sb + 32768 + off);
                LDSM_X4(bl, sb + 49152 + off);
#pragma unroll
                for (int t = 0; t < 2; t++) {
#pragma unroll
                    for (int jj = 0; jj < 2; jj++) {
                        float* d = acc[t][jp * 2 + jj];
                        MMA_BF16(d, ah[t], bh[jj * 2], bh[jj * 2 + 1]);
                        MMA_BF16(d, ah[t], bl[jj * 2], bl[jj * 2 + 1]);
                        MMA_BF16(d, al[t], bh[jj * 2], bh[jj * 2 + 1]);
                    }
                }
            }
        }
        __syncthreads();
    }

    const bool addB = (flags & 1) != 0;
    const bool accum = (flags & 2) != 0;
    const bool splitO = (flags & 4) != 0;
    const bool gateDot = (flags & 8) != 0;
    const bool onehot = (flags & 16) != 0;
#pragma unroll
    for (int t = 0; t < 2; t++) {
        const int r0 = mBase + wm * 32 + t * 16 + (lane >> 2);
        float p0 = 0.f, p1 = 0.f;
#pragma unroll
        for (int j = 0; j < 4; j++) {
            const int col = nBase + wn * 32 + j * 8 + (lane & 3) * 2;
            float b0 = 0.f, b1 = 0.f;
            if (addB) { b0 = bias[col]; b1 = bias[col + 1]; }
            float v0 = acc[t][j][0] + b0, v1 = acc[t][j][1] + b1;
            float v2 = acc[t][j][2] + b0, v3 = acc[t][j][3] + b1;
            const size_t o0 = (size_t)r0 * N + col;
            const size_t o1 = (size_t)(r0 + 8) * N + col;
            if (splitO) {
                __nv_bfloat162 h, lo;
                split2(v0, v1, h, lo);
                *(__nv_bfloat162*)(Ch + o0) = h;
                *(__nv_bfloat162*)(Cl + o0) = lo;
                split2(v2, v3, h, lo);
                *(__nv_bfloat162*)(Ch + o1) = h;
                *(__nv_bfloat162*)(Cl + o1) = lo;
            } else {
                if (onehot) {
                    const int t0 = xTok[r0], t1 = xTok[r0 + 8];
                    v0 += (col == t0) ? 1.f : 0.f;
                    v1 += (col + 1 == t0) ? 1.f : 0.f;
                    v2 += (col == t1) ? 1.f : 0.f;
                    v3 += (col + 1 == t1) ? 1.f : 0.f;
                }
                if (accum) {
                    float2 q0 = *(float2*)(Cf + o0);
                    float2 q1 = *(float2*)(Cf + o1);
                    v0 += q0.x; v1 += q0.y; v2 += q1.x; v3 += q1.y;
                }
                *(float2*)(Cf + o0) = make_float2(v0, v1);
                *(float2*)(Cf + o1) = make_float2(v2, v3);
            }
            if (gateDot) {
                const float w0 = __ldg(wgv + col), w1 = __ldg(wgv + col + 1);
                p0 = fmaf(v0, w0, fmaf(v1, w1, p0));
                p1 = fmaf(v2, w0, fmaf(v3, w1, p1));
            }
        }
        if (gateDot) {
            p0 += __shfl_xor_sync(0xffffffffu, p0, 1);
            p0 += __shfl_xor_sync(0xffffffffu, p0, 2);
            p1 += __shfl_xor_sync(0xffffffffu, p1, 1);
            p1 += __shfl_xor_sync(0xffffffffu, p1, 2);
            if ((lane & 3) == 0) {
                float* gp = gateOut + ((size_t)((nBase >> 7) * 4 + wn)) * Tsz;
                gp[r0] = p0;          // race-free partial store
                gp[r0 + 8] = p1;
            }
        }
    }
}

// ============================================================================
// Fused fc(+folded wout) + gated-MLP GEMM, 512 threads. A = scan output.
// ============================================================================
#define FC_STAGE 98304
#define FCSMEM (2 * FC_STAGE)

__global__ __launch_bounds__(512, 1)
void mma_fc_k(const __nv_bfloat16* __restrict__ Ah, const __nv_bfloat16* __restrict__ Al,
              const __nv_bfloat16* __restrict__ Wh, const __nv_bfloat16* __restrict__ Wl,
              const float* __restrict__ bias,
              __nv_bfloat16* __restrict__ Oh, __nv_bfloat16* __restrict__ Ol) {
    extern __shared__ char smem[];
    const uint32_t smb = smem_u32(smem);
    const int tid = threadIdx.x, lane = tid & 31, wid = tid >> 5;
    const int mBase = blockIdx.y << 7, nBase = blockIdx.x << 7;
    const int wm = wid & 3, wn = wid >> 2;

    float accg[2][4][4], accv[2][4][4];
#pragma unroll
    for (int t = 0; t < 2; t++)
#pragma unroll
        for (int j = 0; j < 4; j++)
#pragma unroll
            for (int q = 0; q < 4; q++) { accg[t][j][q] = 0.f; accv[t][j][q] = 0.f; }

    const int rowIdx = tid >> 3, col16 = tid & 7;

    auto issue = [&](int idx) {
        const int c8 = idx & 7;
        const uint32_t sb = smb + (uint32_t)(idx & 1) * FC_STAGE;
        const int kOff = c8 * 64 + col16 * 8;
#pragma unroll
        for (int c = 0; c < 2; c++) {
            const int row = rowIdx + c * 64;
            const uint32_t dsw = swz((uint32_t)(row * 128 + col16 * 16));
            const size_t aoff = (size_t)(mBase + row) * Dsz + kOff;
            cp16(sb + dsw, Ah + aoff, true);
            cp16(sb + 16384 + dsw, Al + aoff, true);
            const size_t wgoff = (size_t)(nBase + row) * Dsz + kOff;
            cp16(sb + 32768 + dsw, Wh + wgoff, true);
            cp16(sb + 49152 + dsw, Wl + wgoff, true);
            const size_t wvoff = (size_t)(512 + nBase + row) * Dsz + kOff;
            cp16(sb + 65536 + dsw, Wh + wvoff, true);
            cp16(sb + 81920 + dsw, Wl + wvoff, true);
        }
        CP_COMMIT();
    };

    issue(0);
    for (int idx = 0; idx < 8; idx++) {
        if (idx + 1 < 8) {
            issue(idx + 1);
            asm volatile("cp.async.wait_group 1;" ::: "memory");
        } else {
            asm volatile("cp.async.wait_group 0;" ::: "memory");
        }
        __syncthreads();
        const uint32_t sb = smb + (uint32_t)(idx & 1) * FC_STAGE;
#pragma unroll
        for (int kk = 0; kk < 4; kk++) {
            uint32_t ah[2][4], al[2][4];
#pragma unroll
            for (int t = 0; t < 2; t++) {
                const int row = wm * 32 + t * 16 + (lane & 15);
                const uint32_t off =
                    swz((uint32_t)(row * 128 + kk * 32 + (lane >> 4) * 16));
                LDSM_X4(ah[t], sb + off);
                LDSM_X4(al[t], sb + 16384 + off);
            }
#pragma unroll
            for (int jp = 0; jp < 2; jp++) {
                const int nrow = wn * 32 + jp * 16 + (lane & 7) + ((lane >> 4) << 3);
                const uint32_t off =
                    swz((uint32_t)(nrow * 128 + kk * 32 + ((lane >> 3) & 1) * 16));
                {
                    uint32_t bh[4], bl[4];
                    LDSM_X4(bh, sb + 32768 + off);
                    LDSM_X4(bl, sb + 49152 + off);
#pragma unroll
                    for (int t = 0; t < 2; t++)
#pragma unroll
                        for (int jj = 0; jj < 2; jj++) {
                            float* d = accg[t][jp * 2 + jj];
                            MMA_BF16(d, ah[t], bh[jj * 2], bh[jj * 2 + 1]);
                            MMA_BF16(d, ah[t], bl[jj * 2], bl[jj * 2 + 1]);
                            MMA_BF16(d, al[t], bh[jj * 2], bh[jj * 2 + 1]);
                        }
                }
                {
                    uint32_t bh[4], bl[4];
                    LDSM_X4(bh, sb + 65536 + off);
                    LDSM_X4(bl, sb + 81920 + off);
#pragma unroll
                    for (int t = 0; t < 2; t++)
#pragma unroll
                        for (int jj = 0; jj < 2; jj++) {
                            float* d = accv[t][jp * 2 + jj];
                            MMA_BF16(d, ah[t], bh[jj * 2], bh[jj * 2 + 1]);
                            MMA_BF16(d, ah[t], bl[jj * 2], bl[jj * 2 + 1]);
                            MMA_BF16(d, al[t], bh[jj * 2], bh[jj * 2 + 1]);
                        }
                }
            }
        }
        __syncthreads();
    }

#pragma unroll
    for (int t = 0; t < 2; t++) {
#pragma unroll
        for (int j = 0; j < 4; j++) {
            const int r0 = mBase + wm * 32 + t * 16 + (lane >> 2);
            const int col = nBase + wn * 32 + j * 8 + (lane & 3) * 2;
            const float bg0 = bias[col], bg1 = bias[col + 1];
            const float bv0 = bias[512 + col], bv1 = bias[512 + col + 1];
            float s0 = 1.f / (1.f + expf(-(accg[t][j][0] + bg0)));
            float s1 = 1.f / (1.f + expf(-(accg[t][j][1] + bg1)));
            float s2 = 1.f / (1.f + expf(-(accg[t][j][2] + bg0)));
            float s3 = 1.f / (1.f + expf(-(accg[t][j][3] + bg1)));
            float v0 = s0 * (accv[t][j][0] + bv0);
            float v1 = s1 * (accv[t][j][1] + bv1);
            float v2 = s2 * (accv[t][j][2] + bv0);
            float v3 = s3 * (accv[t][j][3] + bv1);
            const size_t o0 = (size_t)r0 * Dsz + col;
            const size_t o1 = (size_t)(r0 + 8) * Dsz + col;
            __nv_bfloat162 h, lo;
            split2(v0, v1, h, lo);
            *(__nv_bfloat162*)(Oh + o0) = h;
            *(__nv_bfloat162*)(Ol + o0) = lo;
            split2(v2, v3, h, lo);
            *(__nv_bfloat162*)(Oh + o1) = h;
            *(__nv_bfloat162*)(Ol + o1) = lo;
        }
    }
}

// ---------------- layer-0 LN: analytic LN of one-hot ------------------------
__global__ void ln0_split_k(const int* __restrict__ x,
                            __nv_bfloat16* __restrict__ oh, __nv_bfloat16* __restrict__ ol,
                            const float* __restrict__ gamma, const float* __restrict__ beta) {
    int t = blockIdx.x, tid = threadIdx.x;
    const int tok = x[t];
    const float mean = 1.0f / 512.0f;
    const float var = (1.0f / 512.0f) * (511.0f / 512.0f);
    const float rstd = rsqrtf(var + 1e-5f);
    float4 g4 = ((const float4*)gamma)[tid];
    float4 b4 = ((const float4*)beta)[tid];
    int d0 = tid * 4;
    float f0 = (((d0 + 0) == tok ? 1.f : 0.f) - mean) * rstd * g4.x + b4.x;
    float f1 = (((d0 + 1) == tok ? 1.f : 0.f) - mean) * rstd * g4.y + b4.y;
    float f2 = (((d0 + 2) == tok ? 1.f : 0.f) - mean) * rstd * g4.z + b4.z;
    float f3 = (((d0 + 3) == tok ? 1.f : 0.f) - mean) * rstd * g4.w + b4.w;
    __nv_bfloat162 h01, l01, h23, l23;
    split2(f0, f1, h01, l01);
    split2(f2, f3, h23, l23);
    __nv_bfloat162* ph = (__nv_bfloat162*)(oh + (size_t)t * Dsz);
    __nv_bfloat162* pl = (__nv_bfloat162*)(ol + (size_t)t * Dsz);
    ph[2 * tid] = h01; ph[2 * tid + 1] = h23;
    pl[2 * tid] = l01; pl[2 * tid + 1] = l23;
}

// ---------------- layernorm with fused bf16 hi/lo split ----------------------
__global__ void ln_split_k(const float* __restrict__ in,
                           __nv_bfloat16* __restrict__ oh, __nv_bfloat16* __restrict__ ol,
                           const float* __restrict__ gamma, const float* __restrict__ beta) {
    int t = blockIdx.x, tid = threadIdx.x;
    const float4* rp = (const float4*)(in + (size_t)t * Dsz);
    float4 v = rp[tid];
    float s = v.x + v.y + v.z + v.w;
#pragma unroll
    for (int o = 16; o; o >>= 1) s += __shfl_xor_sync(0xffffffffu, s, o);
    __shared__ float smr[4];
    if ((tid & 31) == 0) smr[tid >> 5] = s;
    __syncthreads();
    float mean = (smr[0] + smr[1] + smr[2] + smr[3]) * (1.0f / Dsz);
    float dx = v.x - mean, dy = v.y - mean, dz = v.z - mean, dw = v.w - mean;
    float q = dx * dx + dy * dy + dz * dz + dw * dw;
#pragma unroll
    for (int o = 16; o; o >>= 1) q += __shfl_xor_sync(0xffffffffu, q, o);
    __syncthreads();
    if ((tid & 31) == 0) smr[tid >> 5] = q;
    __syncthreads();
    float var = (smr[0] + smr[1] + smr[2] + smr[3]) * (1.0f / Dsz);
    float rstd = rsqrtf(var + 1e-5f);
    float4 g4 = ((const float4*)gamma)[tid];
    float4 b4 = ((const float4*)beta)[tid];
    float f0 = dx * rstd * g4.x + b4.x, f1 = dy * rstd * g4.y + b4.y;
    float f2 = dz * rstd * g4.z + b4.z, f3 = dw * rstd * g4.w + b4.w;
    __nv_bfloat162 h01, l01, h23, l23;
    split2(f0, f1, h01, l01);
    split2(f2, f3, h23, l23);
    __nv_bfloat162* ph = (__nv_bfloat162*)(oh + (size_t)t * Dsz);
    __nv_bfloat162* pl = (__nv_bfloat162*)(ol + (size_t)t * Dsz);
    ph[2 * tid] = h01; ph[2 * tid + 1] = h23;
    pl[2 * tid] = l01; pl[2 * tid + 1] = l23;
}

// ---------------- conv weight repack + split ---------------------------------
__global__ void cwsplit_k(const float* __restrict__ cw,
                          __nv_bfloat16* __restrict__ wh, __nv_bfloat16* __restrict__ wl) {
    int idx = blockIdx.x * blockDim.x + threadIdx.x;
    int layer = idx / (3 * DD);
    int r = idx - layer * (3 * DD);
    int h = r / DD;
    int rr = r - h * DD;
    int o = rr >> 9, i = rr & 511;
    float v = cw[(size_t)layer * 3 * DD + ((size_t)o * Dsz + i) * 3 + h];
    __nv_bfloat16 hi = __float2bfloat16(v);
    wh[idx] = hi;
    wl[idx] = __float2bfloat16(v - __bfloat162float(hi));
}

// ---------------- generic weight split ---------------------------------------
__global__ void wsplit_k(const float* __restrict__ w, __nv_bfloat16* __restrict__ wh,
                         __nv_bfloat16* __restrict__ wl, int n) {
    int idx = blockIdx.x * blockDim.x + threadIdx.x;
    if (idx >= n) return;
    float v = w[idx];
    __nv_bfloat16 hi = __float2bfloat16(v);
    wh[idx] = hi;
    wl[idx] = __float2bfloat16(v - __bfloat162float(hi));
}

// ---------------- transpose-split: out[l][n*512+k] = w[l][k*512+n] -----------
__global__ void wsplit_t_k(const float* __restrict__ w, __nv_bfloat16* __restrict__ wh,
                           __nv_bfloat16* __restrict__ wl) {
    int idx = blockIdx.x * blockDim.x + threadIdx.x;  // over NL*DD
    int layer = idx / DD;
    int r = idx - layer * DD;
    int n = r >> 9, k = r & 511;
    float v = w[(size_t)layer * DD + (size_t)k * Dsz + n];
    __nv_bfloat16 hi = __float2bfloat16(v);
    wh[idx] = hi;
    wl[idx] = __float2bfloat16(v - __bfloat162float(hi));
}

// ---------------- bcomb = Wf·bo + fb (warp per output) -----------------------
__global__ void bcomb_k(const float* __restrict__ fw, const float* __restrict__ bo,
                        const float* __restrict__ fb, float* __restrict__ out) {
    int w = (blockIdx.x * blockDim.x + threadIdx.x) >> 5;  // 0..NL*1024-1
    int lane = threadIdx.x & 31;
    int layer = w >> 10, e = w & 1023;
    const float* fr = fw + ((size_t)layer * 1024 + e) * Dsz;
    const float* br = bo + (size_t)layer * Dsz;
    float s = 0.f;
#pragma unroll
    for (int i = 0; i < 16; i++) s = fmaf(fr[lane + 32 * i], br[lane + 32 * i], s);
#pragma unroll
    for (int o = 16; o; o >>= 1) s += __shfl_xor_sync(0xffffffffu, s, o);
    if (lane == 0) out[w] = s + fb[(size_t)layer * 1024 + e];
}

// ---------------- gate finish: sum 16 partials + sigmoid ----------------------
__global__ void sigmoid_gate_k(const float* __restrict__ gp, float* __restrict__ g,
                               const float* __restrict__ bg) {
    int t = blockIdx.x * blockDim.x + threadIdx.x;
    float s = 0.f;
#pragma unroll
    for (int p = 0; p < 16; p++) s += gp[(size_t)p * Tsz + t];
    g[t] = 1.0f / (1.0f + expf(-(s + bg[0])));
}

// ---------------- chunked scan: phase 1 ---------------------------------------
__global__ void scan1_k(const float* __restrict__ x, const float* __restrict__ g,
                        float* __restrict__ hend, float* __restrict__ aprod) {
    int bx = blockIdx.x;
    int c = bx >> 6;
    int rem = bx & 63;
    int b = rem >> 2;
    int d = ((rem & 3) << 7) + threadIdx.x;
    size_t base = (size_t)b * Lsz * Dsz + d;
    const float* gb = g + (size_t)b * Lsz;
    const int l0 = c * SCH;
    float hv = 0.f, ap = 1.f;
    for (int l = l0; l < l0 + SCH; l += 8) {
        float xs[8], gs[8];
#pragma unroll
        for (int j = 0; j < 8; j++) {
            xs[j] = x[base + (size_t)(l + j) * Dsz];
            gs[j] = gb[l + j];
        }
#pragma unroll
        for (int j = 0; j < 8; j++) {
            hv = fmaf(gs[j], xs[j] - hv, hv);
            ap *= (1.f - gs[j]);
        }
    }
    const size_t o = (size_t)c * (Bsz * Dsz) + (size_t)b * Dsz + d;
    hend[o] = hv;
    aprod[o] = ap;
}

// ---------------- chunked scan: phase 2+3 fused (carry inline) -----------------
__global__ void scan3_k(const float* __restrict__ x, const float* __restrict__ g,
                        const float* __restrict__ hend, const float* __restrict__ aprod,
                        __nv_bfloat16* __restrict__ hh, __nv_bfloat16* __restrict__ hl) {
    int bx = blockIdx.x;
    int c = bx >> 6;
    int rem = bx & 63;
    int b = rem >> 2;
    int d = ((rem & 3) << 7) + threadIdx.x;
    size_t base = (size_t)b * Lsz * Dsz + d;
    const float* gb = g + (size_t)b * Lsz;
    float hv = 0.f;
    for (int cc = 0; cc < c; cc++) {
        const size_t o = (size_t)cc * (Bsz * Dsz) + (size_t)b * Dsz + d;
        hv = hend[o] + aprod[o] * hv;
    }
    const int l0 = c * SCH;
    for (int l = l0; l < l0 + SCH; l += 8) {
        float xs[8], gs[8];
#pragma unroll
        for (int j = 0; j < 8; j++) {
            xs[j] = x[base + (size_t)(l + j) * Dsz];
            gs[j] = gb[l + j];
        }
#pragma unroll
        for (int j = 0; j < 8; j++) {
            hv = fmaf(gs[j], xs[j] - hv, hv);
            __nv_bfloat16 hi = __float2bfloat16(hv);
            size_t o = base + (size_t)(l + j) * Dsz;
            hh[o] = hi;
            hl[o] = __float2bfloat16(hv - __bfloat162float(hi));
        }
    }
}

// ---------------- launch --------------------------------------------------------
extern "C" void kernel_launch(void* const* d_in, const int* in_sizes, int n_in,
                              void* d_out, int out_size) {
    const int* x = (const int*)d_in[0];
    const float* ln_g = (const float*)d_in[1];
    const float* ln_b = (const float*)d_in[2];
    const float* conv_w = (const float*)d_in[3];
    const float* conv_b = (const float*)d_in[4];
    const float* wg = (const float*)d_in[5];
    const float* bg = (const float*)d_in[6];
    const float* wout = (const float*)d_in[7];
    const float* bout = (const float*)d_in[8];
    const float* fc_w = (const float*)d_in[9];
    const float* fc_b = (const float*)d_in[10];
    const float* mo_w = (const float*)d_in[11];
    const float* mo_b = (const float*)d_in[12];
    const float* lnf_g = (const float*)d_in[13];
    const float* lnf_b = (const float*)d_in[14];
    const float* head_w = (const float*)d_in[15];
    const float* head_b = (const float*)d_in[16];

    float *y, *z2, *gt, *gp, *bcomb, *hend, *aprod;
    __nv_bfloat16 *zh, *zl, *hh, *hl, *gh, *gl, *wh, *wl;
    cudaGetSymbolAddress((void**)&y, g_y);
    cudaGetSymbolAddress((void**)&z2, g_z2);
    cudaGetSymbolAddress((void**)&gt, g_gate);
    cudaGetSymbolAddress((void**)&gp, g_gatep);
    cudaGetSymbolAddress((void**)&bcomb, g_bcomb);
    cudaGetSymbolAddress((void**)&hend, g_hend);
    cudaGetSymbolAddress((void**)&aprod, g_aprod);
    cudaGetSymbolAddress((void**)&zh, g_zh);
    cudaGetSymbolAddress((void**)&zl, g_zl);
    cudaGetSymbolAddress((void**)&hh, g_hh);
    cudaGetSymbolAddress((void**)&hl, g_hl);
    cudaGetSymbolAddress((void**)&gh, g_gh);
    cudaGetSymbolAddress((void**)&gl, g_gl);
    cudaGetSymbolAddress((void**)&wh, g_wh);
    cudaGetSymbolAddress((void**)&wl, g_wl);

    cudaFuncSetAttribute(mma_gemm_k, cudaFuncAttributeMaxDynamicSharedMemorySize, GSMEM);
    cudaFuncSetAttribute(mma_fc_k, cudaFuncAttributeMaxDynamicSharedMemorySize, FCSMEM);

    const dim3 g512(4, Tsz / 128);

    // ---- one-time: weight splits + wout-into-fc folding ----
    cwsplit_k<<<(NLsz * 3 * DD) / 256, 256>>>(conv_w, wh + W_CONV(0), wl + W_CONV(0));
    wsplit_k<<<(NLsz * 2 * DD) / 256, 256>>>(fc_w, wh + W_FC(0), wl + W_FC(0), NLsz * 2 * DD);
    wsplit_t_k<<<(NLsz * DD) / 256, 256>>>(wout, wh + W_WOUT(0), wl + W_WOUT(0));
    wsplit_k<<<(NLsz * DD) / 256, 256>>>(mo_w, wh + W_MO(0), wl + W_MO(0), NLsz * DD);
    wsplit_k<<<DD / 256, 256>>>(head_w, wh + W_HEAD, wl + W_HEAD, DD);
    bcomb_k<<<(NLsz * 1024 * 32) / 256, 256>>>(fc_w, bout, fc_b, bcomb);
    // Wcomb = Wf @ Wo  (batched over 4 layers: M = 4096 rows, W steps DD per 1024 rows)
    mma_gemm_k<<<dim3(4, 32), 512, GSMEM>>>(wh + W_FC(0), wl + W_FC(0),
                                            wh + W_WOUT(0), wl + W_WOUT(0),
                                            nullptr, z2, nullptr, nullptr,
                                            nullptr, nullptr, nullptr,
                                            Dsz, 1, 0, 0, 0, 0, (int)DD);
    wsplit_k<<<(8 * DD) / 256, 256>>>(z2, wh + W_FC(0), wl + W_FC(0), 8 * DD);

    for (int i = 0; i < NLsz; i++) {
        if (i == 0)
            ln0_split_k<<<Tsz, 128>>>(x, zh, zl, ln_g, ln_b);
        else
            ln_split_k<<<Tsz, 128>>>(y, zh, zl, ln_g + (size_t)i * Dsz, ln_b + (size_t)i * Dsz);
        // conv: 3 shifted passes, epilogue emits race-free gate partials
        mma_gemm_k<<<g512, 512, GSMEM>>>(zh, zl, wh + W_CONV(i), wl + W_CONV(i),
                                         conv_b + (size_t)i * Dsz, z2, nullptr, nullptr,
                                         wg + (size_t)i * Dsz, nullptr, gp,
                                         Dsz, 3, -1, 0, 1, 1 | 8, 0);
        sigmoid_gate_k<<<Tsz / 256, 256>>>(gp, gt, bg + i);
        scan1_k<<<NCH * 64, 128>>>(z2, gt, hend, aprod);
        scan3_k<<<NCH * 64, 128>>>(z2, gt, hend, aprod, hh, hl);
        // fc(+folded wout) + gated-MLP fused: reads scan output directly
        mma_fc_k<<<g512, 512, FCSMEM>>>(hh, hl, wh + W_FC(i), wl + W_FC(i),
                                        bcomb + (size_t)i * 1024, gh, gl);
        // mo: layer 0 adds analytic one-hot residual; others accumulate y
        mma_gemm_k<<<g512, 512, GSMEM>>>(gh, gl, wh + W_MO(i), wl + W_MO(i),
                                         mo_b + (size_t)i * Dsz, y, nullptr, nullptr,
                                         nullptr, (i == 0) ? x : nullptr, nullptr,
                                         Dsz, 1, 0, 0, 0, (i == 0) ? (1 | 16) : (1 | 2), 0);
    }

    ln_split_k<<<Tsz, 128>>>(y, zh, zl, lnf_g, lnf_b);
    mma_gemm_k<<<g512, 512, GSMEM>>>(zh, zl, wh + W_HEAD, wl + W_HEAD, head_b,
                                     (float*)d_out, nullptr, nullptr,
                                     nullptr, nullptr, nullptr, Dsz, 1, 0, 0, 0, 1, 0);
}

// round 8
// speedup vs baseline: 1.2971x; 1.1190x over previous
#include <cuda_runtime.h>
#include <cuda_bf16.h>
#include <cstdint>
#include <cstddef>

#define Bsz 16
#define Lsz 2048
#define Dsz 512
#define NLsz 4
#define Tsz (Bsz * Lsz)  // 32768
#define DD (Dsz * Dsz)

// weight arena offsets (units of DD)
#define W_CONV(i) ((size_t)(i) * 3 * DD)
#define W_WOUT(i) ((size_t)(12 + (i)) * DD)      // wout^T (prep only)
#define W_FC(i)   ((size_t)(16 + 2 * (i)) * DD)  // after prep: Wcomb = Wf@Wo
#define W_MO(i)   ((size_t)(24 + (i)) * DD)
#define W_HEAD    ((size_t)28 * DD)

// scan chunking
#define SCH 256
#define NCH (Lsz / SCH)  // 8

// ---------------- scratch (device globals; no allocation allowed) ----------
__device__ float g_y[Tsz * Dsz];
__device__ float g_z2[Tsz * Dsz];
__device__ float g_gate[Tsz];
__device__ float g_gatep[16 * Tsz];
__device__ float g_bcomb[NLsz * 2 * Dsz];
__device__ float g_hend[NCH * Bsz * Dsz];
__device__ float g_aprod[NCH * Bsz * Dsz];
__device__ float g_w0t[3 * DD];           // layer-0 conv taps, transposed [h][i][o]
__device__ float g_u0[3 * Dsz];           // layer-0 per-tap constant W_h^T v
__device__ __nv_bfloat16 g_zh[Tsz * Dsz], g_zl[Tsz * Dsz];
__device__ __nv_bfloat16 g_hh[Tsz * Dsz], g_hl[Tsz * Dsz];
__device__ __nv_bfloat16 g_gh[Tsz * Dsz], g_gl[Tsz * Dsz];
__device__ __nv_bfloat16 g_wh[29 * DD], g_wl[29 * DD];

// ---------------- helpers ---------------------------------------------------
__device__ __forceinline__ uint32_t smem_u32(const void* p) {
    return (uint32_t)__cvta_generic_to_shared(p);
}
__device__ __forceinline__ uint32_t swz(uint32_t x) { return x ^ ((x >> 3) & 0x70); }

__device__ __forceinline__ void cp16(uint32_t dst, const void* src, bool v) {
    int sz = v ? 16 : 0;
    asm volatile("cp.async.cg.shared.global [%0], [%1], 16, %2;"
                 :: "r"(dst), "l"(src), "r"(sz) : "memory");
}
#define CP_COMMIT() asm volatile("cp.async.commit_group;" ::: "memory")

#define LDSM_X4(r, a)                                                          \
    asm volatile("ldmatrix.sync.aligned.m8n8.x4.shared.b16 {%0,%1,%2,%3}, [%4];" \
                 : "=r"((r)[0]), "=r"((r)[1]), "=r"((r)[2]), "=r"((r)[3]) : "r"(a))

#define MMA_BF16(d, a, b0, b1)                                                 \
    asm volatile(                                                              \
        "mma.sync.aligned.m16n8k16.row.col.f32.bf16.bf16.f32 "                 \
        "{%0,%1,%2,%3},{%4,%5,%6,%7},{%8,%9},{%0,%1,%2,%3};"                   \
        : "+f"((d)[0]), "+f"((d)[1]), "+f"((d)[2]), "+f"((d)[3])               \
        : "r"((a)[0]), "r"((a)[1]), "r"((a)[2]), "r"((a)[3]), "r"(b0), "r"(b1))

__device__ __forceinline__ void split2(float a, float b, __nv_bfloat162& hi,
                                       __nv_bfloat162& lo) {
    hi = __floats2bfloat162_rn(a, b);
    lo = __floats2bfloat162_rn(a - __bfloat162float(hi.x), b - __bfloat162float(hi.y));
}

// ============================================================================
// Generic bf16-split GEMM, 512 threads, tile 128x128, single-sync pipeline.
// flags: 1=addBias, 2=accum fp32, 4=split bf16 out, 8=gate partials,
//        16=one-hot residual add.
// ============================================================================
#define STAGE_B 65536
#define GSMEM (3 * STAGE_B)

__global__ __launch_bounds__(512, 1)
void mma_gemm_k(const __nv_bfloat16* __restrict__ Ah, const __nv_bfloat16* __restrict__ Al,
                const __nv_bfloat16* __restrict__ Wh, const __nv_bfloat16* __restrict__ Wl,
                const float* __restrict__ bias, float* __restrict__ Cf,
                __nv_bfloat16* __restrict__ Ch, __nv_bfloat16* __restrict__ Cl,
                const float* __restrict__ wgv, const int* __restrict__ xTok,
                float* __restrict__ gateOut,
                int N, int nPasses, int s0, int s1, int s2, int flags,
                int wLayerStride) {
    extern __shared__ char smem[];
    const uint32_t smb = smem_u32(smem);
    const int tid = threadIdx.x, lane = tid & 31, wid = tid >> 5;
    const int mBase = blockIdx.y << 7, nBase = blockIdx.x << 7;
    const int wm = wid & 3, wn = wid >> 2;

    float acc[2][4][4];
#pragma unroll
    for (int t = 0; t < 2; t++)
#pragma unroll
        for (int j = 0; j < 4; j++)
#pragma unroll
            for (int q = 0; q < 4; q++) acc[t][j][q] = 0.f;

    const int total = nPasses * 8;
    const int rowIdx = tid >> 3, col16 = tid & 7;

    auto issue = [&](int idx) {
        const int p = idx >> 3, c8 = idx & 7;
        const int shift = (p == 0) ? s0 : ((p == 1) ? s1 : s2);
        const size_t wOff = (size_t)p * DD + (size_t)(mBase >> 10) * wLayerStride;
        const uint32_t sb = smb + (uint32_t)(idx % 3) * STAGE_B;
        const int kOff = c8 * 64 + col16 * 8;
#pragma unroll
        for (int c = 0; c < 2; c++) {
            const int row = rowIdx + c * 64;
            const uint32_t dsw = swz((uint32_t)(row * 128 + col16 * 16));
            const int m = mBase + row;
            const int l = m & (Lsz - 1);
            const bool valid = ((unsigned)(l + shift) < (unsigned)Lsz);
            const size_t aoff = (size_t)(m + (valid ? shift : 0)) * Dsz + kOff;
            cp16(sb + dsw, Ah + aoff, valid);
            cp16(sb + 16384 + dsw, Al + aoff, valid);
            const size_t woff = wOff + (size_t)(nBase + row) * Dsz + kOff;
            cp16(sb + 32768 + dsw, Wh + woff, true);
            cp16(sb + 49152 + dsw, Wl + woff, true);
        }
        CP_COMMIT();
    };

    issue(0);
    if (total > 1) issue(1);
    for (int idx = 0; idx < total; idx++) {
        if (idx + 1 < total) {
            asm volatile("cp.async.wait_group 1;" ::: "memory");
        } else {
            asm volatile("cp.async.wait_group 0;" ::: "memory");
        }
        __syncthreads();
        if (idx + 2 < total) issue(idx + 2);
        const uint32_t sb = smb + (uint32_t)(idx % 3) * STAGE_B;
#pragma unroll
        for (int kk = 0; kk < 4; kk++) {
            uint32_t ah[2][4], al[2][4];
#pragma unroll
            for (int t = 0; t < 2; t++) {
                const int row = wm * 32 + t * 16 + (lane & 15);
                const uint32_t off =
                    swz((uint32_t)(row * 128 + kk * 32 + (lane >> 4) * 16));
                LDSM_X4(ah[t], sb + off);
                LDSM_X4(al[t], sb + 16384 + off);
            }
#pragma unroll
            for (int jp = 0; jp < 2; jp++) {
                const int nrow = wn * 32 + jp * 16 + (lane & 7) + ((lane >> 4) << 3);
                const uint32_t off =
                    swz((uint32_t)(nrow * 128 + kk * 32 + ((lane >> 3) & 1) * 16));
                uint32_t bh[4], bl[4];
                LDSM_X4(bh, sb + 32768 + off);
                LDSM_X4(bl, sb + 49152 + off);
#pragma unroll
                for (int t = 0; t < 2; t++) {
#pragma unroll
                    for (int jj = 0; jj < 2; jj++) {
                        float* d = acc[t][jp * 2 + jj];
                        MMA_BF16(d, ah[t], bh[jj * 2], bh[jj * 2 + 1]);
                        MMA_BF16(d, ah[t], bl[jj * 2], bl[jj * 2 + 1]);
                        MMA_BF16(d, al[t], bh[jj * 2], bh[jj * 2 + 1]);
                    }
                }
            }
        }
    }

    const bool addB = (flags & 1) != 0;
    const bool accum = (flags & 2) != 0;
    const bool splitO = (flags & 4) != 0;
    const bool gateDot = (flags & 8) != 0;
    const bool onehot = (flags & 16) != 0;
#pragma unroll
    for (int t = 0; t < 2; t++) {
        const int r0 = mBase + wm * 32 + t * 16 + (lane >> 2);
        float p0 = 0.f, p1 = 0.f;
#pragma unroll
        for (int j = 0; j < 4; j++) {
            const int col = nBase + wn * 32 + j * 8 + (lane & 3) * 2;
            float b0 = 0.f, b1 = 0.f;
            if (addB) { b0 = bias[col]; b1 = bias[col + 1]; }
            float v0 = acc[t][j][0] + b0, v1 = acc[t][j][1] + b1;
            float v2 = acc[t][j][2] + b0, v3 = acc[t][j][3] + b1;
            const size_t o0 = (size_t)r0 * N + col;
            const size_t o1 = (size_t)(r0 + 8) * N + col;
            if (splitO) {
                __nv_bfloat162 h, lo;
                split2(v0, v1, h, lo);
                *(__nv_bfloat162*)(Ch + o0) = h;
                *(__nv_bfloat162*)(Cl + o0) = lo;
                split2(v2, v3, h, lo);
                *(__nv_bfloat162*)(Ch + o1) = h;
                *(__nv_bfloat162*)(Cl + o1) = lo;
            } else {
                if (onehot) {
                    const int t0 = xTok[r0], t1 = xTok[r0 + 8];
                    v0 += (col == t0) ? 1.f : 0.f;
                    v1 += (col + 1 == t0) ? 1.f : 0.f;
                    v2 += (col == t1) ? 1.f : 0.f;
                    v3 += (col + 1 == t1) ? 1.f : 0.f;
                }
                if (accum) {
                    float2 q0 = *(float2*)(Cf + o0);
                    float2 q1 = *(float2*)(Cf + o1);
                    v0 += q0.x; v1 += q0.y; v2 += q1.x; v3 += q1.y;
                }
                *(float2*)(Cf + o0) = make_float2(v0, v1);
                *(float2*)(Cf + o1) = make_float2(v2, v3);
            }
            if (gateDot) {
                const float w0 = __ldg(wgv + col), w1 = __ldg(wgv + col + 1);
                p0 = fmaf(v0, w0, fmaf(v1, w1, p0));
                p1 = fmaf(v2, w0, fmaf(v3, w1, p1));
            }
        }
        if (gateDot) {
            p0 += __shfl_xor_sync(0xffffffffu, p0, 1);
            p0 += __shfl_xor_sync(0xffffffffu, p0, 2);
            p1 += __shfl_xor_sync(0xffffffffu, p1, 1);
            p1 += __shfl_xor_sync(0xffffffffu, p1, 2);
            if ((lane & 3) == 0) {
                float* gp = gateOut + ((size_t)((nBase >> 7) * 4 + wn)) * Tsz;
                gp[r0] = p0;
                gp[r0 + 8] = p1;
            }
        }
    }
}

// ============================================================================
// Fused fc(+folded wout) + gated-MLP GEMM, 512 threads, single-sync pipeline.
// ============================================================================
#define FC_STAGE 98304
#define FCSMEM (2 * FC_STAGE)

__global__ __launch_bounds__(512, 1)
void mma_fc_k(const __nv_bfloat16* __restrict__ Ah, const __nv_bfloat16* __restrict__ Al,
              const __nv_bfloat16* __restrict__ Wh, const __nv_bfloat16* __restrict__ Wl,
              const float* __restrict__ bias,
              __nv_bfloat16* __restrict__ Oh, __nv_bfloat16* __restrict__ Ol) {
    extern __shared__ char smem[];
    const uint32_t smb = smem_u32(smem);
    const int tid = threadIdx.x, lane = tid & 31, wid = tid >> 5;
    const int mBase = blockIdx.y << 7, nBase = blockIdx.x << 7;
    const int wm = wid & 3, wn = wid >> 2;

    float accg[2][4][4], accv[2][4][4];
#pragma unroll
    for (int t = 0; t < 2; t++)
#pragma unroll
        for (int j = 0; j < 4; j++)
#pragma unroll
            for (int q = 0; q < 4; q++) { accg[t][j][q] = 0.f; accv[t][j][q] = 0.f; }

    const int rowIdx = tid >> 3, col16 = tid & 7;

    auto issue = [&](int idx) {
        const int c8 = idx & 7;
        const uint32_t sb = smb + (uint32_t)(idx & 1) * FC_STAGE;
        const int kOff = c8 * 64 + col16 * 8;
#pragma unroll
        for (int c = 0; c < 2; c++) {
            const int row = rowIdx + c * 64;
            const uint32_t dsw = swz((uint32_t)(row * 128 + col16 * 16));
            const size_t aoff = (size_t)(mBase + row) * Dsz + kOff;
            cp16(sb + dsw, Ah + aoff, true);
            cp16(sb + 16384 + dsw, Al + aoff, true);
            const size_t wgoff = (size_t)(nBase + row) * Dsz + kOff;
            cp16(sb + 32768 + dsw, Wh + wgoff, true);
            cp16(sb + 49152 + dsw, Wl + wgoff, true);
            const size_t wvoff = (size_t)(512 + nBase + row) * Dsz + kOff;
            cp16(sb + 65536 + dsw, Wh + wvoff, true);
            cp16(sb + 81920 + dsw, Wl + wvoff, true);
        }
        CP_COMMIT();
    };

    issue(0);
    for (int idx = 0; idx < 8; idx++) {
        asm volatile("cp.async.wait_group 0;" ::: "memory");
        __syncthreads();
        if (idx + 1 < 8) issue(idx + 1);
        const uint32_t sb = smb + (uint32_t)(idx & 1) * FC_STAGE;
#pragma unroll
        for (int kk = 0; kk < 4; kk++) {
            uint32_t ah[2][4], al[2][4];
#pragma unroll
            for (int t = 0; t < 2; t++) {
                const int row = wm * 32 + t * 16 + (lane & 15);
                const uint32_t off =
                    swz((uint32_t)(row * 128 + kk * 32 + (lane >> 4) * 16));
                LDSM_X4(ah[t], sb + off);
                LDSM_X4(al[t], sb + 16384 + off);
            }
#pragma unroll
            for (int jp = 0; jp < 2; jp++) {
                const int nrow = wn * 32 + jp * 16 + (lane & 7) + ((lane >> 4) << 3);
                const uint32_t off =
                    swz((uint32_t)(nrow * 128 + kk * 32 + ((lane >> 3) & 1) * 16));
                {
                    uint32_t bh[4], bl[4];
                    LDSM_X4(bh, sb + 32768 + off);
                    LDSM_X4(bl, sb + 49152 + off);
#pragma unroll
                    for (int t = 0; t < 2; t++)
#pragma unroll
                        for (int jj = 0; jj < 2; jj++) {
                            float* d = accg[t][jp * 2 + jj];
                            MMA_BF16(d, ah[t], bh[jj * 2], bh[jj * 2 + 1]);
                            MMA_BF16(d, ah[t], bl[jj * 2], bl[jj * 2 + 1]);
                            MMA_BF16(d, al[t], bh[jj * 2], bh[jj * 2 + 1]);
                        }
                }
                {
                    uint32_t bh[4], bl[4];
                    LDSM_X4(bh, sb + 65536 + off);
                    LDSM_X4(bl, sb + 81920 + off);
#pragma unroll
                    for (int t = 0; t < 2; t++)
#pragma unroll
                        for (int jj = 0; jj < 2; jj++) {
                            float* d = accv[t][jp * 2 + jj];
                            MMA_BF16(d, ah[t], bh[jj * 2], bh[jj * 2 + 1]);
                            MMA_BF16(d, ah[t], bl[jj * 2], bl[jj * 2 + 1]);
                            MMA_BF16(d, al[t], bh[jj * 2], bh[jj * 2 + 1]);
                        }
                }
            }
        }
    }

#pragma unroll
    for (int t = 0; t < 2; t++) {
#pragma unroll
        for (int j = 0; j < 4; j++) {
            const int r0 = mBase + wm * 32 + t * 16 + (lane >> 2);
            const int col = nBase + wn * 32 + j * 8 + (lane & 3) * 2;
            const float bg0 = bias[col], bg1 = bias[col + 1];
            const float bv0 = bias[512 + col], bv1 = bias[512 + col + 1];
            float s0 = 1.f / (1.f + expf(-(accg[t][j][0] + bg0)));
            float s1 = 1.f / (1.f + expf(-(accg[t][j][1] + bg1)));
            float s2 = 1.f / (1.f + expf(-(accg[t][j][2] + bg0)));
            float s3 = 1.f / (1.f + expf(-(accg[t][j][3] + bg1)));
            float v0 = s0 * (accv[t][j][0] + bv0);
            float v1 = s1 * (accv[t][j][1] + bv1);
            float v2 = s2 * (accv[t][j][2] + bv0);
            float v3 = s3 * (accv[t][j][3] + bv1);
            const size_t o0 = (size_t)r0 * Dsz + col;
            const size_t o1 = (size_t)(r0 + 8) * Dsz + col;
            __nv_bfloat162 h, lo;
            split2(v0, v1, h, lo);
            *(__nv_bfloat162*)(Oh + o0) = h;
            *(__nv_bfloat162*)(Ol + o0) = lo;
            split2(v2, v3, h, lo);
            *(__nv_bfloat162*)(Oh + o1) = h;
            *(__nv_bfloat162*)(Ol + o1) = lo;
        }
    }
}

// ============================================================================
// Layer-0 conv as gather: z2[t] = cb + Σ_valid(h) [ s(tok')·Wt_h[tok'] + u_h ],
// plus fused gate: gt[t] = sigmoid(dot(z2[t], wg) + bg). Exact fp32.
// ============================================================================
__global__ void conv0_k(const int* __restrict__ x, const float* __restrict__ w0t,
                        const float* __restrict__ u0, const float* __restrict__ cb,
                        const float* __restrict__ lng, const float* __restrict__ wgv,
                        const float* __restrict__ bg,
                        float* __restrict__ z2, float* __restrict__ gt) {
    const int t = blockIdx.x, tid = threadIdx.x;  // 128 threads, 4 outputs each
    const int l = t & (Lsz - 1);
    const float mean = 1.0f / 512.0f;
    const float rstd = rsqrtf(mean * (511.0f / 512.0f) + 1e-5f);

    const int tokm = (l > 0) ? x[t - 1] : -1;
    const int tok0 = x[t];
    const int tokp = (l < Lsz - 1) ? x[t + 1] : -1;

    float4 acc = ((const float4*)cb)[tid];
    // tap h=1 (center) always valid
    {
        const float s = rstd * lng[tok0];
        float4 w = ((const float4*)(w0t + (size_t)DD + (size_t)tok0 * Dsz))[tid];
        float4 u = ((const float4*)(u0 + Dsz))[tid];
        acc.x += s * w.x + u.x; acc.y += s * w.y + u.y;
        acc.z += s * w.z + u.z; acc.w += s * w.w + u.w;
    }
    if (tokm >= 0) {  // tap h=0 reads l-1
        const float s = rstd * lng[tokm];
        float4 w = ((const float4*)(w0t + (size_t)tokm * Dsz))[tid];
        float4 u = ((const float4*)u0)[tid];
        acc.x += s * w.x + u.x; acc.y += s * w.y + u.y;
        acc.z += s * w.z + u.z; acc.w += s * w.w + u.w;
    }
    if (tokp >= 0) {  // tap h=2 reads l+1
        const float s = rstd * lng[tokp];
        float4 w = ((const float4*)(w0t + (size_t)2 * DD + (size_t)tokp * Dsz))[tid];
        float4 u = ((const float4*)(u0 + 2 * Dsz))[tid];
        acc.x += s * w.x + u.x; acc.y += s * w.y + u.y;
        acc.z += s * w.z + u.z; acc.w += s * w.w + u.w;
    }
    ((float4*)(z2 + (size_t)t * Dsz))[tid] = acc;

    // fused gate dot
    float4 wv = ((const float4*)wgv)[tid];
    float p = acc.x * wv.x + acc.y * wv.y + acc.z * wv.z + acc.w * wv.w;
#pragma unroll
    for (int o = 16; o; o >>= 1) p += __shfl_xor_sync(0xffffffffu, p, o);
    __shared__ float smr[4];
    if ((tid & 31) == 0) smr[tid >> 5] = p;
    __syncthreads();
    if (tid == 0) {
        float s = smr[0] + smr[1] + smr[2] + smr[3];
        gt[t] = 1.0f / (1.0f + expf(-(s + bg[0])));
    }
}

// ---------------- layer-0 conv prep: transpose taps + constant vectors -------
__global__ void w0t_k(const float* __restrict__ cw, float* __restrict__ w0t) {
    int idx = blockIdx.x * blockDim.x + threadIdx.x;  // over 3*DD
    int h = idx / DD;
    int r = idx - h * DD;
    int i = r >> 9, o = r & 511;
    w0t[idx] = cw[((size_t)o * Dsz + i) * 3 + h];
}
__global__ void u0_k(const float* __restrict__ cw, const float* __restrict__ lng,
                     const float* __restrict__ lnb, float* __restrict__ u0) {
    int w = (blockIdx.x * blockDim.x + threadIdx.x) >> 5;  // 0..3*512-1
    int lane = threadIdx.x & 31;
    int h = w >> 9, o = w & 511;
    const float mean = 1.0f / 512.0f;
    const float rstd = rsqrtf(mean * (511.0f / 512.0f) + 1e-5f);
    float s = 0.f;
#pragma unroll
    for (int c = 0; c < 16; c++) {
        int i = lane + 32 * c;
        float v = lnb[i] - rstd * mean * lng[i];
        s = fmaf(cw[((size_t)o * Dsz + i) * 3 + h], v, s);
    }
#pragma unroll
    for (int ofs = 16; ofs; ofs >>= 1) s += __shfl_xor_sync(0xffffffffu, s, ofs);
    if (lane == 0) u0[w] = s;
}

// ---------------- layernorm with fused bf16 hi/lo split ----------------------
__global__ void ln_split_k(const float* __restrict__ in,
                           __nv_bfloat16* __restrict__ oh, __nv_bfloat16* __restrict__ ol,
                           const float* __restrict__ gamma, const float* __restrict__ beta) {
    int t = blockIdx.x, tid = threadIdx.x;
    const float4* rp = (const float4*)(in + (size_t)t * Dsz);
    float4 v = rp[tid];
    float s = v.x + v.y + v.z + v.w;
#pragma unroll
    for (int o = 16; o; o >>= 1) s += __shfl_xor_sync(0xffffffffu, s, o);
    __shared__ float smr[4];
    if ((tid & 31) == 0) smr[tid >> 5] = s;
    __syncthreads();
    float mean = (smr[0] + smr[1] + smr[2] + smr[3]) * (1.0f / Dsz);
    float dx = v.x - mean, dy = v.y - mean, dz = v.z - mean, dw = v.w - mean;
    float q = dx * dx + dy * dy + dz * dz + dw * dw;
#pragma unroll
    for (int o = 16; o; o >>= 1) q += __shfl_xor_sync(0xffffffffu, q, o);
    __syncthreads();
    if ((tid & 31) == 0) smr[tid >> 5] = q;
    __syncthreads();
    float var = (smr[0] + smr[1] + smr[2] + smr[3]) * (1.0f / Dsz);
    float rstd = rsqrtf(var + 1e-5f);
    float4 g4 = ((const float4*)gamma)[tid];
    float4 b4 = ((const float4*)beta)[tid];
    float f0 = dx * rstd * g4.x + b4.x, f1 = dy * rstd * g4.y + b4.y;
    float f2 = dz * rstd * g4.z + b4.z, f3 = dw * rstd * g4.w + b4.w;
    __nv_bfloat162 h01, l01, h23, l23;
    split2(f0, f1, h01, l01);
    split2(f2, f3, h23, l23);
    __nv_bfloat162* ph = (__nv_bfloat162*)(oh + (size_t)t * Dsz);
    __nv_bfloat162* pl = (__nv_bfloat162*)(ol + (size_t)t * Dsz);
    ph[2 * tid] = h01; ph[2 * tid + 1] = h23;
    pl[2 * tid] = l01; pl[2 * tid + 1] = l23;
}

// ---------------- conv weight repack + split ---------------------------------
__global__ void cwsplit_k(const float* __restrict__ cw,
                          __nv_bfloat16* __restrict__ wh, __nv_bfloat16* __restrict__ wl) {
    int idx = blockIdx.x * blockDim.x + threadIdx.x;
    int layer = idx / (3 * DD);
    int r = idx - layer * (3 * DD);
    int h = r / DD;
    int rr = r - h * DD;
    int o = rr >> 9, i = rr & 511;
    float v = cw[(size_t)layer * 3 * DD + ((size_t)o * Dsz + i) * 3 + h];
    __nv_bfloat16 hi = __float2bfloat16(v);
    wh[idx] = hi;
    wl[idx] = __float2bfloat16(v - __bfloat162float(hi));
}

// ---------------- generic weight split ---------------------------------------
__global__ void wsplit_k(const float* __restrict__ w, __nv_bfloat16* __restrict__ wh,
                         __nv_bfloat16* __restrict__ wl, int n) {
    int idx = blockIdx.x * blockDim.x + threadIdx.x;
    if (idx >= n) return;
    float v = w[idx];
    __nv_bfloat16 hi = __float2bfloat16(v);
    wh[idx] = hi;
    wl[idx] = __float2bfloat16(v - __bfloat162float(hi));
}

// ---------------- transpose-split: out[l][n*512+k] = w[l][k*512+n] -----------
__global__ void wsplit_t_k(const float* __restrict__ w, __nv_bfloat16* __restrict__ wh,
                           __nv_bfloat16* __restrict__ wl) {
    int idx = blockIdx.x * blockDim.x + threadIdx.x;
    int layer = idx / DD;
    int r = idx - layer * DD;
    int n = r >> 9, k = r & 511;
    float v = w[(size_t)layer * DD + (size_t)k * Dsz + n];
    __nv_bfloat16 hi = __float2bfloat16(v);
    wh[idx] = hi;
    wl[idx] = __float2bfloat16(v - __bfloat162float(hi));
}

// ---------------- bcomb = Wf·bo + fb ------------------------------------------
__global__ void bcomb_k(const float* __restrict__ fw, const float* __restrict__ bo,
                        const float* __restrict__ fb, float* __restrict__ out) {
    int w = (blockIdx.x * blockDim.x + threadIdx.x) >> 5;
    int lane = threadIdx.x & 31;
    int layer = w >> 10, e = w & 1023;
    const float* fr = fw + ((size_t)layer * 1024 + e) * Dsz;
    const float* br = bo + (size_t)layer * Dsz;
    float s = 0.f;
#pragma unroll
    for (int i = 0; i < 16; i++) s = fmaf(fr[lane + 32 * i], br[lane + 32 * i], s);
#pragma unroll
    for (int o = 16; o; o >>= 1) s += __shfl_xor_sync(0xffffffffu, s, o);
    if (lane == 0) out[w] = s + fb[(size_t)layer * 1024 + e];
}

// ---------------- gate finish: sum 16 partials + sigmoid ----------------------
__global__ void sigmoid_gate_k(const float* __restrict__ gp, float* __restrict__ g,
                               const float* __restrict__ bg) {
    int t = blockIdx.x * blockDim.x + threadIdx.x;
    float s = 0.f;
#pragma unroll
    for (int p = 0; p < 16; p++) s += gp[(size_t)p * Tsz + t];
    g[t] = 1.0f / (1.0f + expf(-(s + bg[0])));
}

// ---------------- chunked scan: phase 1 ---------------------------------------
__global__ void scan1_k(const float* __restrict__ x, const float* __restrict__ g,
                        float* __restrict__ hend, float* __restrict__ aprod) {
    int bx = blockIdx.x;
    int c = bx >> 6;
    int rem = bx & 63;
    int b = rem >> 2;
    int d = ((rem & 3) << 7) + threadIdx.x;
    size_t base = (size_t)b * Lsz * Dsz + d;
    const float* gb = g + (size_t)b * Lsz;
    const int l0 = c * SCH;
    float hv = 0.f, ap = 1.f;
    for (int l = l0; l < l0 + SCH; l += 8) {
        float xs[8], gs[8];
#pragma unroll
        for (int j = 0; j < 8; j++) {
            xs[j] = x[base + (size_t)(l + j) * Dsz];
            gs[j] = gb[l + j];
        }
#pragma unroll
        for (int j = 0; j < 8; j++) {
            hv = fmaf(gs[j], xs[j] - hv, hv);
            ap *= (1.f - gs[j]);
        }
    }
    const size_t o = (size_t)c * (Bsz * Dsz) + (size_t)b * Dsz + d;
    hend[o] = hv;
    aprod[o] = ap;
}

// ---------------- chunked scan: phase 2+3 fused --------------------------------
__global__ void scan3_k(const float* __restrict__ x, const float* __restrict__ g,
                        const float* __restrict__ hend, const float* __restrict__ aprod,
                        __nv_bfloat16* __restrict__ hh, __nv_bfloat16* __restrict__ hl) {
    int bx = blockIdx.x;
    int c = bx >> 6;
    int rem = bx & 63;
    int b = rem >> 2;
    int d = ((rem & 3) << 7) + threadIdx.x;
    size_t base = (size_t)b * Lsz * Dsz + d;
    const float* gb = g + (size_t)b * Lsz;
    float hv = 0.f;
    for (int cc = 0; cc < c; cc++) {
        const size_t o = (size_t)cc * (Bsz * Dsz) + (size_t)b * Dsz + d;
        hv = hend[o] + aprod[o] * hv;
    }
    const int l0 = c * SCH;
    for (int l = l0; l < l0 + SCH; l += 8) {
        float xs[8], gs[8];
#pragma unroll
        for (int j = 0; j < 8; j++) {
            xs[j] = x[base + (size_t)(l + j) * Dsz];
            gs[j] = gb[l + j];
        }
#pragma unroll
        for (int j = 0; j < 8; j++) {
            hv = fmaf(gs[j], xs[j] - hv, hv);
            __nv_bfloat16 hi = __float2bfloat16(hv);
            size_t o = base + (size_t)(l + j) * Dsz;
            hh[o] = hi;
            hl[o] = __float2bfloat16(hv - __bfloat162float(hi));
        }
    }
}

// ---------------- launch --------------------------------------------------------
extern "C" void kernel_launch(void* const* d_in, const int* in_sizes, int n_in,
                              void* d_out, int out_size) {
    const int* x = (const int*)d_in[0];
    const float* ln_g = (const float*)d_in[1];
    const float* ln_b = (const float*)d_in[2];
    const float* conv_w = (const float*)d_in[3];
    const float* conv_b = (const float*)d_in[4];
    const float* wg = (const float*)d_in[5];
    const float* bg = (const float*)d_in[6];
    const float* wout = (const float*)d_in[7];
    const float* bout = (const float*)d_in[8];
    const float* fc_w = (const float*)d_in[9];
    const float* fc_b = (const float*)d_in[10];
    const float* mo_w = (const float*)d_in[11];
    const float* mo_b = (const float*)d_in[12];
    const float* lnf_g = (const float*)d_in[13];
    const float* lnf_b = (const float*)d_in[14];
    const float* head_w = (const float*)d_in[15];
    const float* head_b = (const float*)d_in[16];

    float *y, *z2, *gt, *gp, *bcomb, *hend, *aprod, *w0t, *u0;
    __nv_bfloat16 *zh, *zl, *hh, *hl, *gh, *gl, *wh, *wl;
    cudaGetSymbolAddress((void**)&y, g_y);
    cudaGetSymbolAddress((void**)&z2, g_z2);
    cudaGetSymbolAddress((void**)&gt, g_gate);
    cudaGetSymbolAddress((void**)&gp, g_gatep);
    cudaGetSymbolAddress((void**)&bcomb, g_bcomb);
    cudaGetSymbolAddress((void**)&hend, g_hend);
    cudaGetSymbolAddress((void**)&aprod, g_aprod);
    cudaGetSymbolAddress((void**)&w0t, g_w0t);
    cudaGetSymbolAddress((void**)&u0, g_u0);
    cudaGetSymbolAddress((void**)&zh, g_zh);
    cudaGetSymbolAddress((void**)&zl, g_zl);
    cudaGetSymbolAddress((void**)&hh, g_hh);
    cudaGetSymbolAddress((void**)&hl, g_hl);
    cudaGetSymbolAddress((void**)&gh, g_gh);
    cudaGetSymbolAddress((void**)&gl, g_gl);
    cudaGetSymbolAddress((void**)&wh, g_wh);
    cudaGetSymbolAddress((void**)&wl, g_wl);

    cudaFuncSetAttribute(mma_gemm_k, cudaFuncAttributeMaxDynamicSharedMemorySize, GSMEM);
    cudaFuncSetAttribute(mma_fc_k, cudaFuncAttributeMaxDynamicSharedMemorySize, FCSMEM);

    const dim3 g512(4, Tsz / 128);

    // ---- one-time: weight splits, wout-into-fc folding, layer-0 conv tables ----
    cwsplit_k<<<(NLsz * 3 * DD) / 256, 256>>>(conv_w, wh + W_CONV(0), wl + W_CONV(0));
    wsplit_k<<<(NLsz * 2 * DD) / 256, 256>>>(fc_w, wh + W_FC(0), wl + W_FC(0), NLsz * 2 * DD);
    wsplit_t_k<<<(NLsz * DD) / 256, 256>>>(wout, wh + W_WOUT(0), wl + W_WOUT(0));
    wsplit_k<<<(NLsz * DD) / 256, 256>>>(mo_w, wh + W_MO(0), wl + W_MO(0), NLsz * DD);
    wsplit_k<<<DD / 256, 256>>>(head_w, wh + W_HEAD, wl + W_HEAD, DD);
    bcomb_k<<<(NLsz * 1024 * 32) / 256, 256>>>(fc_w, bout, fc_b, bcomb);
    w0t_k<<<(3 * DD) / 256, 256>>>(conv_w, w0t);
    u0_k<<<(3 * Dsz * 32) / 256, 256>>>(conv_w, ln_g, ln_b, u0);
    // Wcomb = Wf @ Wo  (batched over layers)
    mma_gemm_k<<<dim3(4, 32), 512, GSMEM>>>(wh + W_FC(0), wl + W_FC(0),
                                            wh + W_WOUT(0), wl + W_WOUT(0),
                                            nullptr, z2, nullptr, nullptr,
                                            nullptr, nullptr, nullptr,
                                            Dsz, 1, 0, 0, 0, 0, (int)DD);
    wsplit_k<<<(8 * DD) / 256, 256>>>(z2, wh + W_FC(0), wl + W_FC(0), 8 * DD);

    for (int i = 0; i < NLsz; i++) {
        if (i == 0) {
            // layer-0 conv is an exact L2-resident gather with fused gate
            conv0_k<<<Tsz, 128>>>(x, w0t, u0, conv_b, ln_g, wg, bg, z2, gt);
        } else {
            ln_split_k<<<Tsz, 128>>>(y, zh, zl, ln_g + (size_t)i * Dsz, ln_b + (size_t)i * Dsz);
            mma_gemm_k<<<g512, 512, GSMEM>>>(zh, zl, wh + W_CONV(i), wl + W_CONV(i),
                                             conv_b + (size_t)i * Dsz, z2, nullptr, nullptr,
                                             wg + (size_t)i * Dsz, nullptr, gp,
                                             Dsz, 3, -1, 0, 1, 1 | 8, 0);
            sigmoid_gate_k<<<Tsz / 256, 256>>>(gp, gt, bg + i);
        }
        scan1_k<<<NCH * 64, 128>>>(z2, gt, hend, aprod);
        scan3_k<<<NCH * 64, 128>>>(z2, gt, hend, aprod, hh, hl);
        mma_fc_k<<<g512, 512, FCSMEM>>>(hh, hl, wh + W_FC(i), wl + W_FC(i),
                                        bcomb + (size_t)i * 1024, gh, gl);
        mma_gemm_k<<<g512, 512, GSMEM>>>(gh, gl, wh + W_MO(i), wl + W_MO(i),
                                         mo_b + (size_t)i * Dsz, y, nullptr, nullptr,
                                         nullptr, (i == 0) ? x : nullptr, nullptr,
                                         Dsz, 1, 0, 0, 0, (i == 0) ? (1 | 16) : (1 | 2), 0);
    }

    ln_split_k<<<Tsz, 128>>>(y, zh, zl, lnf_g, lnf_b);
    mma_gemm_k<<<g512, 512, GSMEM>>>(zh, zl, wh + W_HEAD, wl + W_HEAD, head_b,
                                     (float*)d_out, nullptr, nullptr,
                                     nullptr, nullptr, nullptr, Dsz, 1, 0, 0, 0, 1, 0);
}